// round 7
// baseline (speedup 1.0000x reference)
#include <cuda_runtime.h>
#include <cuda_bf16.h>
#include <cstdint>
#include <math.h>

#define BATCH 16
#define NMASK 6
#define HW 1089
#define DIM 512
#define NLBL 7
#define INV_T (1.0f/0.07f)
#define SEPM 2.0f
#define UNITH 0.1f

#define CTILES 9          // ceil(1089/128)
#define NTILEPAIRS 45     // CTILES*(CTILES+1)/2
#define CCH 33            // centroid chunks (33 rows each)

// ---- smem layout for supcon_mma (dynamic) ----
#define SM_LROW 0                 // 128 int
#define SM_LCOL 512
#define SM_ROWS 1024
#define SM_ROWP 1536
#define SM_ROWC 2048
#define SM_COLS 2560
#define SM_COLP 3072
#define SM_COLC 3584
#define SM_BUF  4096
#define MATSZ   8192              // 128 rows x 32 bf16 (64B/row)
#define STAGESZ (4*MATSZ)         // Ahi,Alo,Bhi,Blo = 32KB
#define SM_TOTAL (SM_BUF + 2*STAGESZ)   // 69632 -> 2 CTAs/SM

// ---- scratch (device globals: allocation-free) ----
__device__ float g_label_sums[BATCH][NLBL][DIM];
__device__ float g_cnt[BATCH][NLBL];
__device__ float g_q[BATCH][NLBL];
__device__ float g_supcon_sum[BATCH];
__device__ float g_anchor_cnt[BATCH];
__device__ int   g_active[BATCH * NMASK];
__device__ int   g_labels[BATCH * HW];
__device__ float g_rn2[BATCH * HW];
__device__ float g_S[BATCH * HW];
__device__ float g_P[BATCH * HW];
__device__ float g_C[BATCH * HW];
__device__ __align__(16) __nv_bfloat16 g_hi[(size_t)BATCH * HW * DIM];
__device__ __align__(16) __nv_bfloat16 g_lo[(size_t)BATCH * HW * DIM];

// ================= helpers =================
__device__ __forceinline__ uint32_t smem_u32(const void* p) {
    uint32_t a;
    asm("{ .reg .u64 t; cvta.to.shared.u64 t, %1; cvt.u32.u64 %0, t; }" : "=r"(a) : "l"(p));
    return a;
}
__device__ __forceinline__ void ldsm4(uint32_t* r, uint32_t addr) {
    asm volatile("ldmatrix.sync.aligned.m8n8.x4.shared.b16 {%0,%1,%2,%3}, [%4];"
                 : "=r"(r[0]), "=r"(r[1]), "=r"(r[2]), "=r"(r[3]) : "r"(addr));
}
__device__ __forceinline__ void mma_bf16(float* c, const uint32_t* a, const uint32_t* b) {
    asm volatile("mma.sync.aligned.m16n8k16.row.col.f32.bf16.bf16.f32 "
                 "{%0,%1,%2,%3}, {%4,%5,%6,%7}, {%8,%9}, {%0,%1,%2,%3};"
                 : "+f"(c[0]), "+f"(c[1]), "+f"(c[2]), "+f"(c[3])
                 : "r"(a[0]), "r"(a[1]), "r"(a[2]), "r"(a[3]), "r"(b[0]), "r"(b[1]));
}

// ---------------------------------------------------------------------------
// zero: clear all atomic accumulators
// ---------------------------------------------------------------------------
__global__ void zero_kernel() {
    int i = blockIdx.x * blockDim.x + threadIdx.x;
    if (i < BATCH * NLBL * DIM) ((float*)g_label_sums)[i] = 0.f;
    if (i < BATCH * NLBL) { ((float*)g_cnt)[i] = 0.f; ((float*)g_q)[i] = 0.f; }
    if (i < BATCH * HW) { g_S[i] = 0.f; g_P[i] = 0.f; g_C[i] = 0.f; }
}

// ---------------------------------------------------------------------------
// prep: per-(b,m) mask channel sums -> active flags
// ---------------------------------------------------------------------------
__global__ void prep_kernel(const float* __restrict__ masks) {
    int blk = blockIdx.x;
    const float* m = masks + (size_t)blk * HW;
    float s = 0.f;
    for (int i = threadIdx.x; i < HW; i += blockDim.x) s += m[i];
    __shared__ float sh[256];
    sh[threadIdx.x] = s;
    __syncthreads();
    for (int o = 128; o > 0; o >>= 1) {
        if (threadIdx.x < o) sh[threadIdx.x] += sh[threadIdx.x + o];
        __syncthreads();
    }
    if (threadIdx.x == 0) g_active[blk] = (sh[0] > 0.f) ? 1 : 0;
}

// ---------------------------------------------------------------------------
// labels
// ---------------------------------------------------------------------------
__global__ void labels_kernel(const float* __restrict__ masks) {
    int idx = blockIdx.x * blockDim.x + threadIdx.x;
    if (idx >= BATCH * HW) return;
    int b = idx / HW, n = idx - b * HW;
    const float* mb = masks + (size_t)b * NMASK * HW;
    int lbl = 0;
#pragma unroll
    for (int m = 0; m < NMASK; m++) {
        if (mb[(size_t)m * HW + n] > 0.5f && g_active[b * NMASK + m]) lbl = m + 1;
    }
    g_labels[idx] = lbl;
}

// ---------------------------------------------------------------------------
// rn2 + fp32 -> bf16 (hi,lo) split conversion. One warp per pixel.
// ---------------------------------------------------------------------------
__global__ void rn2_cvt_kernel(const float* __restrict__ emb) {
    int w = (blockIdx.x * blockDim.x + threadIdx.x) >> 5;
    int lane = threadIdx.x & 31;
    if (w >= BATCH * HW) return;
    const float4* src = (const float4*)(emb + (size_t)w * DIM) + lane * 4;
    __nv_bfloat16 hh[16], ll[16];
    float s = 0.f;
#pragma unroll
    for (int k = 0; k < 4; k++) {
        float4 v = src[k];
        float vv[4] = {v.x, v.y, v.z, v.w};
#pragma unroll
        for (int e = 0; e < 4; e++) {
            float f = vv[e];
            s += f * f;
            __nv_bfloat16 h = __float2bfloat16(f);
            hh[k * 4 + e] = h;
            ll[k * 4 + e] = __float2bfloat16(f - __bfloat162float(h));
        }
    }
#pragma unroll
    for (int o = 16; o > 0; o >>= 1) s += __shfl_xor_sync(0xffffffffu, s, o);
    if (lane == 0) g_rn2[w] = s;
    uint4* dh = (uint4*)(g_hi + (size_t)w * DIM + lane * 16);
    uint4* dl = (uint4*)(g_lo + (size_t)w * DIM + lane * 16);
    dh[0] = ((uint4*)hh)[0]; dh[1] = ((uint4*)hh)[1];
    dl[0] = ((uint4*)ll)[0]; dl[1] = ((uint4*)ll)[1];
}

// ---------------------------------------------------------------------------
// centroids: parallel over (chunk, image). Each block sums 33 rows.
// ---------------------------------------------------------------------------
__global__ void centroid_kernel(const float* __restrict__ emb) {
    int chunk = blockIdx.x;
    int b = blockIdx.y;
    int t = threadIdx.x;
    int r0 = chunk * 33, r1 = r0 + 33;
    const float* fb = emb + (size_t)b * HW * DIM;
    float acc[NLBL];
#pragma unroll
    for (int l = 0; l < NLBL; l++) acc[l] = 0.f;
    for (int n = r0; n < r1; n++) {
        int lbl = g_labels[b * HW + n];
        float v = fb[(size_t)n * DIM + t];
#pragma unroll
        for (int l = 0; l < NLBL; l++) acc[l] += (lbl == l) ? v : 0.f;
    }
#pragma unroll
    for (int l = 0; l < NLBL; l++)
        if (acc[l] != 0.f) atomicAdd(&g_label_sums[b][l][t], acc[l]);
    if (t < NLBL) {
        float c = 0.f, q = 0.f;
        for (int n = r0; n < r1; n++) {
            if (g_labels[b * HW + n] == t) { c += 1.f; q += g_rn2[b * HW + n]; }
        }
        if (c != 0.f) { atomicAdd(&g_cnt[b][t], c); atomicAdd(&g_q[b][t], q); }
    }
}

// ---------------------------------------------------------------------------
// supcon Gram tile via mma.sync bf16 split-precision (hi*hi + hi*lo + lo*hi).
// 128x128 tile per block (symmetric: ct>=rt). K=512 in 16 chunks of 32,
// double-buffered cp.async (2x32KB), register-only epilogue: row sums via
// shfl over lane&3, column sums via shfl over lane>>2 + smem atomics.
// 68KB smem -> 2 CTAs/SM.
// ---------------------------------------------------------------------------
__global__ __launch_bounds__(256, 2) void supcon_mma_kernel() {
    extern __shared__ char smem[];
    uint32_t sb = smem_u32(smem);
    int tid = threadIdx.x;
    int wid = tid >> 5, lane = tid & 31;
    int wr = wid >> 1, wc = wid & 1;
    int b = blockIdx.y;
    int idx = blockIdx.x, rt = 0;
    while (idx >= CTILES - rt) { idx -= CTILES - rt; rt++; }
    int ct = rt + idx;
    bool diag = (ct == rt);
    int row0 = rt * 128, col0 = ct * 128;

    int* lrow = (int*)(smem + SM_LROW);
    int* lcol = (int*)(smem + SM_LCOL);
    float* rowS = (float*)(smem + SM_ROWS);
    float* rowP = (float*)(smem + SM_ROWP);
    float* rowC = (float*)(smem + SM_ROWC);
    float* colS = (float*)(smem + SM_COLS);
    float* colP = (float*)(smem + SM_COLP);
    float* colC = (float*)(smem + SM_COLC);
    if (tid < 128) {
        int r = row0 + tid, c = col0 + tid;
        lrow[tid] = (r < HW) ? g_labels[b * HW + r] : -1;
        lcol[tid] = (c < HW) ? g_labels[b * HW + c] : -2;
        rowS[tid] = 0.f; rowP[tid] = 0.f; rowC[tid] = 0.f;
        colS[tid] = 0.f; colP[tid] = 0.f; colC[tid] = 0.f;
    }

    const __nv_bfloat16* bhp = g_hi + (size_t)b * HW * DIM;
    const __nv_bfloat16* blp = g_lo + (size_t)b * HW * DIM;

    // ---- cp.async stage loader: 4 mats x 8KB, 64B rows, xor swizzle ----
    auto load_stage = [&](int c, int p) {
        uint32_t dst_base = sb + SM_BUF + p * STAGESZ;
#pragma unroll
        for (int it = 0; it < 8; it++) {
            int mat = it >> 1;
            int idxm = tid + 256 * (it & 1);     // 0..511
            int row = idxm >> 2, seg = idxm & 3;
            int grow = ((mat < 2) ? row0 : col0) + row;
            uint32_t sz = (grow < HW) ? 16u : 0u;
            int gcl = (grow < HW) ? grow : 0;
            const __nv_bfloat16* srcb = (mat & 1) ? blp : bhp;
            const __nv_bfloat16* src = srcb + (size_t)gcl * DIM + c * 32 + seg * 8;
            uint32_t dst = dst_base + mat * MATSZ + row * 64 +
                           (((uint32_t)(seg * 16)) ^ (((uint32_t)row & 3u) << 4));
            asm volatile("cp.async.cg.shared.global [%0], [%1], 16, %2;"
                         :: "r"(dst), "l"(src), "r"(sz) : "memory");
        }
        asm volatile("cp.async.commit_group;" ::: "memory");
    };

    // fragment address components (64B rows, swizzle mask (row&3)<<4)
    int a_r = wr * 32 + (lane & 15);
    uint32_t a_xm = (((uint32_t)lane) & 3u) << 4;
    uint32_t a_kb = (uint32_t)((lane >> 4) * 16);
    int b_n = wc * 64 + ((lane >> 4) & 1) * 8 + (lane & 7);
    uint32_t b_xm = (((uint32_t)lane) & 3u) << 4;
    uint32_t b_kb = (uint32_t)(((lane >> 3) & 1) * 16);

    float acc[2][8][4];
#pragma unroll
    for (int mt = 0; mt < 2; mt++)
#pragma unroll
        for (int nt = 0; nt < 8; nt++)
#pragma unroll
            for (int e = 0; e < 4; e++) acc[mt][nt][e] = 0.f;

    load_stage(0, 0);
    for (int c = 0; c < 16; c++) {
        int p = c & 1;
        if (c + 1 < 16) {
            load_stage(c + 1, p ^ 1);
            asm volatile("cp.async.wait_group 1;" ::: "memory");
        } else {
            asm volatile("cp.async.wait_group 0;" ::: "memory");
        }
        __syncthreads();
        uint32_t stg = sb + SM_BUF + p * STAGESZ;
#pragma unroll
        for (int ks = 0; ks < 2; ks++) {
            uint32_t ka = (((uint32_t)(ks * 32)) + a_kb) ^ a_xm;
            uint32_t ah[2][4], al[2][4];
#pragma unroll
            for (int mt = 0; mt < 2; mt++) {
                uint32_t ad = stg + (uint32_t)((a_r + mt * 16) * 64) + ka;
                ldsm4(ah[mt], ad);
                ldsm4(al[mt], ad + MATSZ);
            }
            uint32_t kb2 = (((uint32_t)(ks * 32)) + b_kb) ^ b_xm;
#pragma unroll
            for (int ntp = 0; ntp < 4; ntp++) {
                uint32_t bh4[4], bl4[4];
                uint32_t bd = stg + 2 * MATSZ + (uint32_t)((b_n + ntp * 16) * 64) + kb2;
                ldsm4(bh4, bd);
                ldsm4(bl4, bd + MATSZ);
#pragma unroll
                for (int mt = 0; mt < 2; mt++) {
                    mma_bf16(acc[mt][2 * ntp],     ah[mt], &bh4[0]);
                    mma_bf16(acc[mt][2 * ntp],     ah[mt], &bl4[0]);
                    mma_bf16(acc[mt][2 * ntp],     al[mt], &bh4[0]);
                    mma_bf16(acc[mt][2 * ntp + 1], ah[mt], &bh4[2]);
                    mma_bf16(acc[mt][2 * ntp + 1], ah[mt], &bl4[2]);
                    mma_bf16(acc[mt][2 * ntp + 1], al[mt], &bh4[2]);
                }
            }
        }
        __syncthreads();
    }

    // ---- register epilogue: rows via shfl(lane&3), cols via shfl(lane>>2) ----
    int lr4 = lane >> 2;
    float S[4], P[4], C4[4];
    int rloc[4], rl[4];
#pragma unroll
    for (int q = 0; q < 4; q++) {
        rloc[q] = wr * 32 + (q >> 1) * 16 + (q & 1) * 8 + lr4;
        rl[q] = lrow[rloc[q]];
        S[q] = P[q] = C4[q] = 0.f;
    }
#pragma unroll
    for (int mt = 0; mt < 2; mt++)
#pragma unroll
        for (int nt = 0; nt < 8; nt++) {
            int cl0 = wc * 64 + nt * 8 + (lane & 3) * 2;
            int c0l = lcol[cl0], c1l = lcol[cl0 + 1];
            int cg0 = col0 + cl0, cg1 = cg0 + 1;
            float Sc0 = 0.f, Pc0 = 0.f, Cc0 = 0.f;
            float Sc1 = 0.f, Pc1 = 0.f, Cc1 = 0.f;
#pragma unroll
            for (int h = 0; h < 2; h++) {
                int q = mt * 2 + h;
                int rg = row0 + rloc[q];
                float d0 = acc[mt][nt][h * 2 + 0], d1 = acc[mt][nt][h * 2 + 1];
                float x0 = (d0 - 1.0f) * INV_T, x1 = (d1 - 1.0f) * INV_T;
                float e0 = __expf(x0), e1 = __expf(x1);
                if (rg < HW && cg0 < HW && cg0 != rg) {
                    S[q] += e0; Sc0 += e0;
                    if (c0l == rl[q]) { P[q] += x0; C4[q] += 1.f; Pc0 += x0; Cc0 += 1.f; }
                }
                if (rg < HW && cg1 < HW && cg1 != rg) {
                    S[q] += e1; Sc1 += e1;
                    if (c1l == rl[q]) { P[q] += x1; C4[q] += 1.f; Pc1 += x1; Cc1 += 1.f; }
                }
            }
            if (!diag) {
#pragma unroll
                for (int o = 4; o <= 16; o <<= 1) {
                    Sc0 += __shfl_xor_sync(0xffffffffu, Sc0, o);
                    Pc0 += __shfl_xor_sync(0xffffffffu, Pc0, o);
                    Cc0 += __shfl_xor_sync(0xffffffffu, Cc0, o);
                    Sc1 += __shfl_xor_sync(0xffffffffu, Sc1, o);
                    Pc1 += __shfl_xor_sync(0xffffffffu, Pc1, o);
                    Cc1 += __shfl_xor_sync(0xffffffffu, Cc1, o);
                }
                if (lane < 4) {
                    atomicAdd(&colS[cl0], Sc0);     atomicAdd(&colS[cl0 + 1], Sc1);
                    atomicAdd(&colP[cl0], Pc0);     atomicAdd(&colP[cl0 + 1], Pc1);
                    atomicAdd(&colC[cl0], Cc0);     atomicAdd(&colC[cl0 + 1], Cc1);
                }
            }
        }
#pragma unroll
    for (int q = 0; q < 4; q++) {
#pragma unroll
        for (int o = 1; o <= 2; o <<= 1) {
            S[q]  += __shfl_xor_sync(0xffffffffu, S[q], o);
            P[q]  += __shfl_xor_sync(0xffffffffu, P[q], o);
            C4[q] += __shfl_xor_sync(0xffffffffu, C4[q], o);
        }
    }
    if ((lane & 3) == 0) {
#pragma unroll
        for (int q = 0; q < 4; q++) {
            atomicAdd(&rowS[rloc[q]], S[q]);
            atomicAdd(&rowP[rloc[q]], P[q]);
            atomicAdd(&rowC[rloc[q]], C4[q]);
        }
    }
    __syncthreads();
    if (tid < 128) {
        int rg = row0 + tid;
        if (rg < HW) {
            atomicAdd(&g_S[b * HW + rg], rowS[tid]);
            atomicAdd(&g_P[b * HW + rg], rowP[tid]);
            atomicAdd(&g_C[b * HW + rg], rowC[tid]);
        }
    } else if (!diag) {
        int j = tid - 128;
        int cg = col0 + j;
        if (cg < HW) {
            atomicAdd(&g_S[b * HW + cg], colS[j]);
            atomicAdd(&g_P[b * HW + cg], colP[j]);
            atomicAdd(&g_C[b * HW + cg], colC[j]);
        }
    }
}

// ---------------------------------------------------------------------------
// per-row supcon loss + per-image reduction
// ---------------------------------------------------------------------------
__global__ void supcon_row_kernel() {
    int b = blockIdx.x;
    int t = threadIdx.x;
    float s = 0.f, n = 0.f;
    for (int r = t; r < HW; r += 256) {
        float c = g_C[b * HW + r];
        if (c > 0.f) {
            s += -((g_P[b * HW + r] - c * logf(g_S[b * HW + r] + 1e-6f)) / c);
            n += 1.f;
        }
    }
    __shared__ float sS[256], sN[256];
    sS[t] = s; sN[t] = n;
    __syncthreads();
    for (int o = 128; o > 0; o >>= 1) {
        if (t < o) { sS[t] += sS[t + o]; sN[t] += sN[t + o]; }
        __syncthreads();
    }
    if (t == 0) { g_supcon_sum[b] = sS[0]; g_anchor_cnt[b] = sN[0]; }
}

// ---------------------------------------------------------------------------
// finalize
// ---------------------------------------------------------------------------
__global__ void finalize_kernel(const float* __restrict__ is_forged, float* __restrict__ out) {
    __shared__ float sc[BATCH], scv[BATCH], sp[BATCH], spv[BATCH], un[BATCH], unv[BATCH];
    int t = threadIdx.x;
    if (t < BATCH) {
        int b = t;
        float na = g_anchor_cnt[b];
        float supcon = g_supcon_sum[b] / fmaxf(na, 1.f);
        float supcon_valid = (na > 0.f) ? 1.f : 0.f;

        float cnt[NLBL], cn[NLBL], inv[NLBL];
#pragma unroll
        for (int l = 0; l < NLBL; l++) {
            cnt[l] = g_cnt[b][l];
            inv[l] = 1.f / fmaxf(cnt[l], 1.f);
            float s = 0.f;
            for (int d = 0; d < DIM; d++) {
                float m = g_label_sums[b][l][d] * inv[l];
                s += m * m;
            }
            cn[l] = s;
        }
        float terms = 0.f, npairs = 0.f;
        int npresent = 0;
#pragma unroll
        for (int l = 0; l < NLBL; l++) if (cnt[l] > 0.f) npresent++;
        for (int l1 = 0; l1 < NLBL; l1++) {
            for (int l2 = l1 + 1; l2 < NLBL; l2++) {
                if (cnt[l1] > 0.f && cnt[l2] > 0.f) {
                    float dot = 0.f;
                    for (int d = 0; d < DIM; d++)
                        dot += (g_label_sums[b][l1][d] * inv[l1]) *
                               (g_label_sums[b][l2][d] * inv[l2]);
                    float sq = cn[l1] + cn[l2] - 2.f * dot;
                    float dd = sqrtf(fmaxf(sq, 0.f));
                    terms += fmaxf(SEPM - dd, 0.f);
                    npairs += 1.f;
                }
            }
        }
        float sep = terms / fmaxf(npairs, 1.f);
        float sep_valid = (npresent >= 2) ? 1.f : 0.f;

        float uni, univ;
        if (is_forged[b] >= 0.5f) {
            float inst = 0.f, nl = 0.f;
#pragma unroll
            for (int l = 0; l < NLBL; l++) {
                float var = g_q[b][l] * inv[l] - cn[l];
                if (cnt[l] >= 2.f && var > UNITH) { inst += var - UNITH; nl += 1.f; }
            }
            uni = inst / fmaxf(nl, 1.f);
            univ = (nl > 0.f) ? 1.f : 0.f;
        } else {
            float qall = 0.f;
#pragma unroll
            for (int l = 0; l < NLBL; l++) qall += g_q[b][l];
            float nrm = 0.f;
            for (int d = 0; d < DIM; d++) {
                float s = 0.f;
#pragma unroll
                for (int l = 0; l < NLBL; l++) s += g_label_sums[b][l][d];
                s *= (1.f / (float)HW);
                nrm += s * s;
            }
            float var_all = qall * (1.f / (float)HW) - nrm;
            uni = (var_all > UNITH) ? (var_all - UNITH) : 0.f;
            univ = (var_all > UNITH) ? 1.f : 0.f;
        }

        sc[b] = supcon * supcon_valid; scv[b] = supcon_valid;
        sp[b] = sep * sep_valid;       spv[b] = sep_valid;
        un[b] = uni * univ;            unv[b] = univ;
    }
    __syncthreads();
    if (t == 0) {
        float a = 0.f, av = 0.f, s2 = 0.f, sv = 0.f, u = 0.f, uv = 0.f;
        for (int b = 0; b < BATCH; b++) {
            a += sc[b]; av += scv[b];
            s2 += sp[b]; sv += spv[b];
            u += un[b]; uv += unv[b];
        }
        float supcon = (av > 0.f) ? a / fmaxf(av, 1.f) : 0.f;
        float sep = (sv > 0.f) ? s2 / fmaxf(sv, 1.f) : 0.f;
        float uni = (uv > 0.f) ? u / fmaxf(uv, 1.f) : 0.f;
        out[0] = 1.0f * supcon + 0.5f * sep + 0.5f * uni;
    }
}

// ---------------------------------------------------------------------------
extern "C" void kernel_launch(void* const* d_in, const int* in_sizes, int n_in,
                              void* d_out, int out_size) {
    const float* emb   = (const float*)d_in[0];   // (16,33,33,512) f32
    const float* masks = (const float*)d_in[1];   // (16,6,33,33) f32
    const float* isf   = (const float*)d_in[2];   // (16,) f32
    float* out = (float*)d_out;

    cudaFuncSetAttribute(supcon_mma_kernel,
                         cudaFuncAttributeMaxDynamicSharedMemorySize, SM_TOTAL);

    zero_kernel<<<(BATCH * NLBL * DIM + 255) / 256, 256>>>();
    prep_kernel<<<BATCH * NMASK, 256>>>(masks);
    labels_kernel<<<(BATCH * HW + 255) / 256, 256>>>(masks);
    rn2_cvt_kernel<<<(BATCH * HW * 32 + 255) / 256, 256>>>(emb);
    centroid_kernel<<<dim3(CCH, BATCH), DIM>>>(emb);
    supcon_mma_kernel<<<dim3(NTILEPAIRS, BATCH), 256, SM_TOTAL>>>();
    supcon_row_kernel<<<BATCH, 256>>>();
    finalize_kernel<<<1, 32>>>(isf, out);
}

// round 8
// speedup vs baseline: 3.8016x; 3.8016x over previous
#include <cuda_runtime.h>
#include <cuda_bf16.h>
#include <cstdint>
#include <math.h>

#define BATCH 16
#define NMASK 6
#define HW 1089
#define DIM 512
#define NLBL 7
#define INV_T (1.0f/0.07f)
#define SEPM 2.0f
#define UNITH 0.1f

#define CTILES 9          // ceil(1089/128)
#define NTILEPAIRS 45     // CTILES*(CTILES+1)/2
#define CCH 33            // centroid chunks (33 rows each)
#define NPD 29            // 28 pair-dots + ||mean_all||^2

// ---- smem layout for supcon_mma (dynamic) ----
#define SM_LROW 0                 // 128 int
#define SM_LCOL 512
#define SM_ROWS 1024
#define SM_ROWP 1536
#define SM_ROWC 2048
#define SM_COLS 2560
#define SM_COLP 3072
#define SM_COLC 3584
#define SM_BUF  4096
#define MATSZ   8192              // 128 rows x 32 bf16 (64B/row)
#define STAGESZ (4*MATSZ)         // Ahi,Alo,Bhi,Blo = 32KB
#define SM_TOTAL (SM_BUF + 2*STAGESZ)   // 69632 -> 2 CTAs/SM

// ---- scratch (device globals: allocation-free) ----
__device__ float g_label_sums[BATCH][NLBL][DIM];
__device__ float g_cnt[BATCH][NLBL];
__device__ float g_q[BATCH][NLBL];
__device__ float g_supcon_sum[BATCH];
__device__ float g_anchor_cnt[BATCH];
__device__ float g_pd[BATCH][NPD];
__device__ int   g_active[BATCH * NMASK];
__device__ int   g_labels[BATCH * HW];
__device__ float g_rn2[BATCH * HW];
__device__ float g_S[BATCH * HW];
__device__ float g_P[BATCH * HW];
__device__ float g_C[BATCH * HW];
__device__ __align__(16) __nv_bfloat16 g_hi[(size_t)BATCH * HW * DIM];
__device__ __align__(16) __nv_bfloat16 g_lo[(size_t)BATCH * HW * DIM];

// ================= helpers =================
__device__ __forceinline__ uint32_t smem_u32(const void* p) {
    uint32_t a;
    asm("{ .reg .u64 t; cvta.to.shared.u64 t, %1; cvt.u32.u64 %0, t; }" : "=r"(a) : "l"(p));
    return a;
}
__device__ __forceinline__ void ldsm4(uint32_t* r, uint32_t addr) {
    asm volatile("ldmatrix.sync.aligned.m8n8.x4.shared.b16 {%0,%1,%2,%3}, [%4];"
                 : "=r"(r[0]), "=r"(r[1]), "=r"(r[2]), "=r"(r[3]) : "r"(addr));
}
__device__ __forceinline__ void mma_bf16(float* c, const uint32_t* a, const uint32_t* b) {
    asm volatile("mma.sync.aligned.m16n8k16.row.col.f32.bf16.bf16.f32 "
                 "{%0,%1,%2,%3}, {%4,%5,%6,%7}, {%8,%9}, {%0,%1,%2,%3};"
                 : "+f"(c[0]), "+f"(c[1]), "+f"(c[2]), "+f"(c[3])
                 : "r"(a[0]), "r"(a[1]), "r"(a[2]), "r"(a[3]), "r"(b[0]), "r"(b[1]));
}
__device__ __forceinline__ int PD(int a, int c) { return a * 7 - (a * (a + 1)) / 2 + c; }

// ---------------------------------------------------------------------------
// prep: blocks [0,96) mask-channel active flags; blocks >=96 zero accumulators
// ---------------------------------------------------------------------------
#define ZBLK 224
__global__ void prep_kernel(const float* __restrict__ masks) {
    int blk = blockIdx.x;
    if (blk < BATCH * NMASK) {
        const float* m = masks + (size_t)blk * HW;
        float s = 0.f;
        for (int i = threadIdx.x; i < HW; i += blockDim.x) s += m[i];
        __shared__ float sh[256];
        sh[threadIdx.x] = s;
        __syncthreads();
        for (int o = 128; o > 0; o >>= 1) {
            if (threadIdx.x < o) sh[threadIdx.x] += sh[threadIdx.x + o];
            __syncthreads();
        }
        if (threadIdx.x == 0) g_active[blk] = (sh[0] > 0.f) ? 1 : 0;
    } else {
        int i = (blk - BATCH * NMASK) * 256 + threadIdx.x;
        if (i < BATCH * HW) { g_S[i] = 0.f; g_P[i] = 0.f; g_C[i] = 0.f; }
        if (i < BATCH * NLBL * DIM) ((float*)g_label_sums)[i] = 0.f;
        if (i < BATCH * NLBL) { ((float*)g_cnt)[i] = 0.f; ((float*)g_q)[i] = 0.f; }
    }
}

// ---------------------------------------------------------------------------
// labels
// ---------------------------------------------------------------------------
__global__ void labels_kernel(const float* __restrict__ masks) {
    int idx = blockIdx.x * blockDim.x + threadIdx.x;
    if (idx >= BATCH * HW) return;
    int b = idx / HW, n = idx - b * HW;
    const float* mb = masks + (size_t)b * NMASK * HW;
    int lbl = 0;
#pragma unroll
    for (int m = 0; m < NMASK; m++) {
        if (mb[(size_t)m * HW + n] > 0.5f && g_active[b * NMASK + m]) lbl = m + 1;
    }
    g_labels[idx] = lbl;
}

// ---------------------------------------------------------------------------
// rn2 + fp32 -> bf16 (hi,lo) split conversion. One warp per pixel.
// ---------------------------------------------------------------------------
__global__ void rn2_cvt_kernel(const float* __restrict__ emb) {
    int w = (blockIdx.x * blockDim.x + threadIdx.x) >> 5;
    int lane = threadIdx.x & 31;
    if (w >= BATCH * HW) return;
    const float4* src = (const float4*)(emb + (size_t)w * DIM) + lane * 4;
    __nv_bfloat16 hh[16], ll[16];
    float s = 0.f;
#pragma unroll
    for (int k = 0; k < 4; k++) {
        float4 v = src[k];
        float vv[4] = {v.x, v.y, v.z, v.w};
#pragma unroll
        for (int e = 0; e < 4; e++) {
            float f = vv[e];
            s += f * f;
            __nv_bfloat16 h = __float2bfloat16(f);
            hh[k * 4 + e] = h;
            ll[k * 4 + e] = __float2bfloat16(f - __bfloat162float(h));
        }
    }
#pragma unroll
    for (int o = 16; o > 0; o >>= 1) s += __shfl_xor_sync(0xffffffffu, s, o);
    if (lane == 0) g_rn2[w] = s;
    uint4* dh = (uint4*)(g_hi + (size_t)w * DIM + lane * 16);
    uint4* dl = (uint4*)(g_lo + (size_t)w * DIM + lane * 16);
    dh[0] = ((uint4*)hh)[0]; dh[1] = ((uint4*)hh)[1];
    dl[0] = ((uint4*)ll)[0]; dl[1] = ((uint4*)ll)[1];
}

// ---------------------------------------------------------------------------
// supcon Gram tile via mma.sync bf16 split-precision (hi*hi + hi*lo + lo*hi).
// 128x128 tile per block (symmetric: ct>=rt). K=512 in 16 chunks of 32,
// double-buffered cp.async, register epilogue with symmetric row+col scatter.
// ---------------------------------------------------------------------------
__global__ __launch_bounds__(256, 2) void supcon_mma_kernel() {
    extern __shared__ char smem[];
    uint32_t sb = smem_u32(smem);
    int tid = threadIdx.x;
    int wid = tid >> 5, lane = tid & 31;
    int wr = wid >> 1, wc = wid & 1;
    int b = blockIdx.y;
    int idx = blockIdx.x, rt = 0;
    while (idx >= CTILES - rt) { idx -= CTILES - rt; rt++; }
    int ct = rt + idx;
    bool diag = (ct == rt);
    int row0 = rt * 128, col0 = ct * 128;

    int* lrow = (int*)(smem + SM_LROW);
    int* lcol = (int*)(smem + SM_LCOL);
    float* rowS = (float*)(smem + SM_ROWS);
    float* rowP = (float*)(smem + SM_ROWP);
    float* rowC = (float*)(smem + SM_ROWC);
    float* colS = (float*)(smem + SM_COLS);
    float* colP = (float*)(smem + SM_COLP);
    float* colC = (float*)(smem + SM_COLC);
    if (tid < 128) {
        int r = row0 + tid, c = col0 + tid;
        lrow[tid] = (r < HW) ? g_labels[b * HW + r] : -1;
        lcol[tid] = (c < HW) ? g_labels[b * HW + c] : -2;
        rowS[tid] = 0.f; rowP[tid] = 0.f; rowC[tid] = 0.f;
        colS[tid] = 0.f; colP[tid] = 0.f; colC[tid] = 0.f;
    }

    const __nv_bfloat16* bhp = g_hi + (size_t)b * HW * DIM;
    const __nv_bfloat16* blp = g_lo + (size_t)b * HW * DIM;

    auto load_stage = [&](int c, int p) {
        uint32_t dst_base = sb + SM_BUF + p * STAGESZ;
#pragma unroll
        for (int it = 0; it < 8; it++) {
            int mat = it >> 1;
            int idxm = tid + 256 * (it & 1);     // 0..511
            int row = idxm >> 2, seg = idxm & 3;
            int grow = ((mat < 2) ? row0 : col0) + row;
            uint32_t sz = (grow < HW) ? 16u : 0u;
            int gcl = (grow < HW) ? grow : 0;
            const __nv_bfloat16* srcb = (mat & 1) ? blp : bhp;
            const __nv_bfloat16* src = srcb + (size_t)gcl * DIM + c * 32 + seg * 8;
            uint32_t dst = dst_base + mat * MATSZ + row * 64 +
                           (((uint32_t)(seg * 16)) ^ (((uint32_t)row & 3u) << 4));
            asm volatile("cp.async.cg.shared.global [%0], [%1], 16, %2;"
                         :: "r"(dst), "l"(src), "r"(sz) : "memory");
        }
        asm volatile("cp.async.commit_group;" ::: "memory");
    };

    int a_r = wr * 32 + (lane & 15);
    uint32_t a_xm = (((uint32_t)lane) & 3u) << 4;
    uint32_t a_kb = (uint32_t)((lane >> 4) * 16);
    int b_n = wc * 64 + ((lane >> 4) & 1) * 8 + (lane & 7);
    uint32_t b_xm = (((uint32_t)lane) & 3u) << 4;
    uint32_t b_kb = (uint32_t)(((lane >> 3) & 1) * 16);

    float acc[2][8][4];
#pragma unroll
    for (int mt = 0; mt < 2; mt++)
#pragma unroll
        for (int nt = 0; nt < 8; nt++)
#pragma unroll
            for (int e = 0; e < 4; e++) acc[mt][nt][e] = 0.f;

    load_stage(0, 0);
    for (int c = 0; c < 16; c++) {
        int p = c & 1;
        if (c + 1 < 16) {
            load_stage(c + 1, p ^ 1);
            asm volatile("cp.async.wait_group 1;" ::: "memory");
        } else {
            asm volatile("cp.async.wait_group 0;" ::: "memory");
        }
        __syncthreads();
        uint32_t stg = sb + SM_BUF + p * STAGESZ;
#pragma unroll
        for (int ks = 0; ks < 2; ks++) {
            uint32_t ka = (((uint32_t)(ks * 32)) + a_kb) ^ a_xm;
            uint32_t ah[2][4], al[2][4];
#pragma unroll
            for (int mt = 0; mt < 2; mt++) {
                uint32_t ad = stg + (uint32_t)((a_r + mt * 16) * 64) + ka;
                ldsm4(ah[mt], ad);
                ldsm4(al[mt], ad + MATSZ);
            }
            uint32_t kb2 = (((uint32_t)(ks * 32)) + b_kb) ^ b_xm;
#pragma unroll
            for (int ntp = 0; ntp < 4; ntp++) {
                uint32_t bh4[4], bl4[4];
                uint32_t bd = stg + 2 * MATSZ + (uint32_t)((b_n + ntp * 16) * 64) + kb2;
                ldsm4(bh4, bd);
                ldsm4(bl4, bd + MATSZ);
#pragma unroll
                for (int mt = 0; mt < 2; mt++) {
                    mma_bf16(acc[mt][2 * ntp],     ah[mt], &bh4[0]);
                    mma_bf16(acc[mt][2 * ntp],     ah[mt], &bl4[0]);
                    mma_bf16(acc[mt][2 * ntp],     al[mt], &bh4[0]);
                    mma_bf16(acc[mt][2 * ntp + 1], ah[mt], &bh4[2]);
                    mma_bf16(acc[mt][2 * ntp + 1], ah[mt], &bl4[2]);
                    mma_bf16(acc[mt][2 * ntp + 1], al[mt], &bh4[2]);
                }
            }
        }
        __syncthreads();
    }

    // ---- register epilogue ----
    int lr4 = lane >> 2;
    float S[4], P[4], C4[4];
    int rloc[4], rl[4];
#pragma unroll
    for (int q = 0; q < 4; q++) {
        rloc[q] = wr * 32 + (q >> 1) * 16 + (q & 1) * 8 + lr4;
        rl[q] = lrow[rloc[q]];
        S[q] = P[q] = C4[q] = 0.f;
    }
#pragma unroll
    for (int mt = 0; mt < 2; mt++)
#pragma unroll
        for (int nt = 0; nt < 8; nt++) {
            int cl0 = wc * 64 + nt * 8 + (lane & 3) * 2;
            int c0l = lcol[cl0], c1l = lcol[cl0 + 1];
            int cg0 = col0 + cl0, cg1 = cg0 + 1;
            float Sc0 = 0.f, Pc0 = 0.f, Cc0 = 0.f;
            float Sc1 = 0.f, Pc1 = 0.f, Cc1 = 0.f;
#pragma unroll
            for (int h = 0; h < 2; h++) {
                int q = mt * 2 + h;
                int rg = row0 + rloc[q];
                float d0 = acc[mt][nt][h * 2 + 0], d1 = acc[mt][nt][h * 2 + 1];
                float x0 = (d0 - 1.0f) * INV_T, x1 = (d1 - 1.0f) * INV_T;
                float e0 = __expf(x0), e1 = __expf(x1);
                if (rg < HW && cg0 < HW && cg0 != rg) {
                    S[q] += e0; Sc0 += e0;
                    if (c0l == rl[q]) { P[q] += x0; C4[q] += 1.f; Pc0 += x0; Cc0 += 1.f; }
                }
                if (rg < HW && cg1 < HW && cg1 != rg) {
                    S[q] += e1; Sc1 += e1;
                    if (c1l == rl[q]) { P[q] += x1; C4[q] += 1.f; Pc1 += x1; Cc1 += 1.f; }
                }
            }
            if (!diag) {
#pragma unroll
                for (int o = 4; o <= 16; o <<= 1) {
                    Sc0 += __shfl_xor_sync(0xffffffffu, Sc0, o);
                    Pc0 += __shfl_xor_sync(0xffffffffu, Pc0, o);
                    Cc0 += __shfl_xor_sync(0xffffffffu, Cc0, o);
                    Sc1 += __shfl_xor_sync(0xffffffffu, Sc1, o);
                    Pc1 += __shfl_xor_sync(0xffffffffu, Pc1, o);
                    Cc1 += __shfl_xor_sync(0xffffffffu, Cc1, o);
                }
                if (lane < 4) {
                    atomicAdd(&colS[cl0], Sc0);     atomicAdd(&colS[cl0 + 1], Sc1);
                    atomicAdd(&colP[cl0], Pc0);     atomicAdd(&colP[cl0 + 1], Pc1);
                    atomicAdd(&colC[cl0], Cc0);     atomicAdd(&colC[cl0 + 1], Cc1);
                }
            }
        }
#pragma unroll
    for (int q = 0; q < 4; q++) {
#pragma unroll
        for (int o = 1; o <= 2; o <<= 1) {
            S[q]  += __shfl_xor_sync(0xffffffffu, S[q], o);
            P[q]  += __shfl_xor_sync(0xffffffffu, P[q], o);
            C4[q] += __shfl_xor_sync(0xffffffffu, C4[q], o);
        }
    }
    if ((lane & 3) == 0) {
#pragma unroll
        for (int q = 0; q < 4; q++) {
            atomicAdd(&rowS[rloc[q]], S[q]);
            atomicAdd(&rowP[rloc[q]], P[q]);
            atomicAdd(&rowC[rloc[q]], C4[q]);
        }
    }
    __syncthreads();
    if (tid < 128) {
        int rg = row0 + tid;
        if (rg < HW) {
            atomicAdd(&g_S[b * HW + rg], rowS[tid]);
            atomicAdd(&g_P[b * HW + rg], rowP[tid]);
            atomicAdd(&g_C[b * HW + rg], rowC[tid]);
        }
    } else if (!diag) {
        int j = tid - 128;
        int cg = col0 + j;
        if (cg < HW) {
            atomicAdd(&g_S[b * HW + cg], colS[j]);
            atomicAdd(&g_P[b * HW + cg], colP[j]);
            atomicAdd(&g_C[b * HW + cg], colC[j]);
        }
    }
}

// ---------------------------------------------------------------------------
// centroids: parallel over (chunk, image). Each block sums 33 rows.
// ---------------------------------------------------------------------------
__global__ void centroid_kernel(const float* __restrict__ emb) {
    int chunk = blockIdx.x;
    int b = blockIdx.y;
    int t = threadIdx.x;
    int r0 = chunk * 33, r1 = r0 + 33;
    const float* fb = emb + (size_t)b * HW * DIM;
    float acc[NLBL];
#pragma unroll
    for (int l = 0; l < NLBL; l++) acc[l] = 0.f;
    for (int n = r0; n < r1; n++) {
        int lbl = g_labels[b * HW + n];
        float v = fb[(size_t)n * DIM + t];
#pragma unroll
        for (int l = 0; l < NLBL; l++) acc[l] += (lbl == l) ? v : 0.f;
    }
#pragma unroll
    for (int l = 0; l < NLBL; l++)
        if (acc[l] != 0.f) atomicAdd(&g_label_sums[b][l][t], acc[l]);
    if (t < NLBL) {
        float c = 0.f, q = 0.f;
        for (int n = r0; n < r1; n++) {
            if (g_labels[b * HW + n] == t) { c += 1.f; q += g_rn2[b * HW + n]; }
        }
        if (c != 0.f) { atomicAdd(&g_cnt[b][t], c); atomicAdd(&g_q[b][t], q); }
    }
}

// ---------------------------------------------------------------------------
// per-row supcon loss + per-image reduction
// ---------------------------------------------------------------------------
__global__ void supcon_row_kernel() {
    int b = blockIdx.x;
    int t = threadIdx.x;
    float s = 0.f, n = 0.f;
    for (int r = t; r < HW; r += 256) {
        float c = g_C[b * HW + r];
        if (c > 0.f) {
            s += -((g_P[b * HW + r] - c * logf(g_S[b * HW + r] + 1e-6f)) / c);
            n += 1.f;
        }
    }
    __shared__ float sS[256], sN[256];
    sS[t] = s; sN[t] = n;
    __syncthreads();
    for (int o = 128; o > 0; o >>= 1) {
        if (t < o) { sS[t] += sS[t + o]; sN[t] += sN[t + o]; }
        __syncthreads();
    }
    if (t == 0) { g_supcon_sum[b] = sS[0]; g_anchor_cnt[b] = sN[0]; }
}

// ---------------------------------------------------------------------------
// pairdot: per-image, 512 threads (thread = dim). Computes the 28 centroid
// pair-dots (incl self-norms) and ||mean_all||^2 in parallel.
// ---------------------------------------------------------------------------
__global__ void pairdot_kernel() {
    int b = blockIdx.x;
    int t = threadIdx.x;
    int lane = t & 31, wrp = t >> 5;
    float inv[NLBL];
#pragma unroll
    for (int l = 0; l < NLBL; l++) inv[l] = 1.f / fmaxf(g_cnt[b][l], 1.f);
    float raw[NLBL], m[NLBL];
    float sall = 0.f;
#pragma unroll
    for (int l = 0; l < NLBL; l++) {
        raw[l] = g_label_sums[b][l][t];
        m[l] = raw[l] * inv[l];
        sall += raw[l];
    }
    sall *= (1.f / (float)HW);
    float part[NPD];
    int k = 0;
#pragma unroll
    for (int l1 = 0; l1 < NLBL; l1++)
#pragma unroll
        for (int l2 = l1; l2 < NLBL; l2++) part[k++] = m[l1] * m[l2];
    part[28] = sall * sall;
#pragma unroll
    for (int i = 0; i < NPD; i++)
#pragma unroll
        for (int o = 16; o > 0; o >>= 1) part[i] += __shfl_xor_sync(0xffffffffu, part[i], o);
    __shared__ float acc[NPD];
    if (t < NPD) acc[t] = 0.f;
    __syncthreads();
    if (lane == 0) {
#pragma unroll
        for (int i = 0; i < NPD; i++) atomicAdd(&acc[i], part[i]);
    }
    __syncthreads();
    if (t < NPD) g_pd[b][t] = acc[t];
    (void)wrp;
}

// ---------------------------------------------------------------------------
// finalize: pure scalar math from precomputed reductions
// ---------------------------------------------------------------------------
__global__ void finalize_kernel(const float* __restrict__ is_forged, float* __restrict__ out) {
    __shared__ float sc[BATCH], scv[BATCH], sp[BATCH], spv[BATCH], un[BATCH], unv[BATCH];
    int t = threadIdx.x;
    if (t < BATCH) {
        int b = t;
        float na = g_anchor_cnt[b];
        float supcon = g_supcon_sum[b] / fmaxf(na, 1.f);
        float supcon_valid = (na > 0.f) ? 1.f : 0.f;

        float pd[NPD];
#pragma unroll
        for (int i = 0; i < NPD; i++) pd[i] = g_pd[b][i];
        float cnt[NLBL], cn[NLBL], inv[NLBL];
#pragma unroll
        for (int l = 0; l < NLBL; l++) {
            cnt[l] = g_cnt[b][l];
            inv[l] = 1.f / fmaxf(cnt[l], 1.f);
            cn[l] = pd[PD(l, l)];
        }
        float terms = 0.f, npairs = 0.f;
        int npresent = 0;
#pragma unroll
        for (int l = 0; l < NLBL; l++) if (cnt[l] > 0.f) npresent++;
#pragma unroll
        for (int l1 = 0; l1 < NLBL; l1++)
#pragma unroll
            for (int l2 = l1 + 1; l2 < NLBL; l2++) {
                if (cnt[l1] > 0.f && cnt[l2] > 0.f) {
                    float sq = cn[l1] + cn[l2] - 2.f * pd[PD(l1, l2)];
                    float dd = sqrtf(fmaxf(sq, 0.f));
                    terms += fmaxf(SEPM - dd, 0.f);
                    npairs += 1.f;
                }
            }
        float sep = terms / fmaxf(npairs, 1.f);
        float sep_valid = (npresent >= 2) ? 1.f : 0.f;

        float uni, univ;
        if (is_forged[b] >= 0.5f) {
            float inst = 0.f, nl = 0.f;
#pragma unroll
            for (int l = 0; l < NLBL; l++) {
                float var = g_q[b][l] * inv[l] - cn[l];
                if (cnt[l] >= 2.f && var > UNITH) { inst += var - UNITH; nl += 1.f; }
            }
            uni = inst / fmaxf(nl, 1.f);
            univ = (nl > 0.f) ? 1.f : 0.f;
        } else {
            float qall = 0.f;
#pragma unroll
            for (int l = 0; l < NLBL; l++) qall += g_q[b][l];
            float var_all = qall * (1.f / (float)HW) - pd[28];
            uni = (var_all > UNITH) ? (var_all - UNITH) : 0.f;
            univ = (var_all > UNITH) ? 1.f : 0.f;
        }

        sc[b] = supcon * supcon_valid; scv[b] = supcon_valid;
        sp[b] = sep * sep_valid;       spv[b] = sep_valid;
        un[b] = uni * univ;            unv[b] = univ;
    }
    __syncthreads();
    if (t == 0) {
        float a = 0.f, av = 0.f, s2 = 0.f, sv = 0.f, u = 0.f, uv = 0.f;
        for (int b = 0; b < BATCH; b++) {
            a += sc[b]; av += scv[b];
            s2 += sp[b]; sv += spv[b];
            u += un[b]; uv += unv[b];
        }
        float supcon = (av > 0.f) ? a / fmaxf(av, 1.f) : 0.f;
        float sep = (sv > 0.f) ? s2 / fmaxf(sv, 1.f) : 0.f;
        float uni = (uv > 0.f) ? u / fmaxf(uv, 1.f) : 0.f;
        out[0] = 1.0f * supcon + 0.5f * sep + 0.5f * uni;
    }
}

// ---------------------------------------------------------------------------
extern "C" void kernel_launch(void* const* d_in, const int* in_sizes, int n_in,
                              void* d_out, int out_size) {
    const float* emb   = (const float*)d_in[0];   // (16,33,33,512) f32
    const float* masks = (const float*)d_in[1];   // (16,6,33,33) f32
    const float* isf   = (const float*)d_in[2];   // (16,) f32
    float* out = (float*)d_out;

    cudaFuncSetAttribute(supcon_mma_kernel,
                         cudaFuncAttributeMaxDynamicSharedMemorySize, SM_TOTAL);

    prep_kernel<<<BATCH * NMASK + ZBLK, 256>>>(masks);                 // 0
    labels_kernel<<<(BATCH * HW + 255) / 256, 256>>>(masks);           // 1
    rn2_cvt_kernel<<<(BATCH * HW * 32 + 255) / 256, 256>>>(emb);       // 2
    supcon_mma_kernel<<<dim3(NTILEPAIRS, BATCH), 256, SM_TOTAL>>>();   // 3 (ncu slot)
    centroid_kernel<<<dim3(CCH, BATCH), DIM>>>(emb);                   // 4
    supcon_row_kernel<<<BATCH, 256>>>();                               // 5
    pairdot_kernel<<<BATCH, DIM>>>();                                  // 6
    finalize_kernel<<<1, 32>>>(isf, out);                              // 7
}

// round 9
// speedup vs baseline: 6.7381x; 1.7724x over previous
#include <cuda_runtime.h>
#include <cuda_fp16.h>
#include <cstdint>
#include <math.h>

#define BATCH 16
#define NMASK 6
#define HW 1089
#define DIM 512
#define NLBL 7
#define INV_T (1.0f/0.07f)
#define SEPM 2.0f
#define UNITH 0.1f

#define CTILES 9          // ceil(1089/128)
#define NTILEPAIRS 45     // CTILES*(CTILES+1)/2
#define CCH 33            // centroid chunks (33 rows each)
#define NPD 29            // 28 pair-dots + ||mean_all||^2

// ---- smem layout for supcon_mma (dynamic) ----
#define SM_LROW 0                 // 128 int
#define SM_LCOL 512
#define SM_ROWS 1024
#define SM_ROWP 1536
#define SM_ROWC 2048
#define SM_COLS 2560
#define SM_COLP 3072
#define SM_COLC 3584
#define SM_BUF  4096
#define MATSZ   16384             // 128 rows x 64 fp16 (128B/row)
#define STAGESZ (2*MATSZ)         // A,B = 32KB
#define SM_TOTAL (SM_BUF + 2*STAGESZ)   // 69632 -> 2 CTAs/SM

// ---- scratch (device globals: allocation-free) ----
__device__ float g_label_sums[BATCH][NLBL][DIM];
__device__ float g_cnt[BATCH][NLBL];
__device__ float g_q[BATCH][NLBL];
__device__ float g_supcon_sum[BATCH];
__device__ float g_anchor_cnt[BATCH];
__device__ float g_pd[BATCH][NPD];
__device__ int   g_active[BATCH * NMASK];
__device__ int   g_labels[BATCH * HW];
__device__ float g_rn2[BATCH * HW];
__device__ float g_S[BATCH * HW];
__device__ float g_P[BATCH * HW];
__device__ float g_C[BATCH * HW];
__device__ __align__(16) __half g_h[(size_t)BATCH * HW * DIM];

// ================= helpers =================
__device__ __forceinline__ uint32_t smem_u32(const void* p) {
    uint32_t a;
    asm("{ .reg .u64 t; cvta.to.shared.u64 t, %1; cvt.u32.u64 %0, t; }" : "=r"(a) : "l"(p));
    return a;
}
__device__ __forceinline__ void ldsm4(uint32_t* r, uint32_t addr) {
    asm volatile("ldmatrix.sync.aligned.m8n8.x4.shared.b16 {%0,%1,%2,%3}, [%4];"
                 : "=r"(r[0]), "=r"(r[1]), "=r"(r[2]), "=r"(r[3]) : "r"(addr));
}
__device__ __forceinline__ void mma_f16(float* c, const uint32_t* a, const uint32_t* b) {
    asm volatile("mma.sync.aligned.m16n8k16.row.col.f32.f16.f16.f32 "
                 "{%0,%1,%2,%3}, {%4,%5,%6,%7}, {%8,%9}, {%0,%1,%2,%3};"
                 : "+f"(c[0]), "+f"(c[1]), "+f"(c[2]), "+f"(c[3])
                 : "r"(a[0]), "r"(a[1]), "r"(a[2]), "r"(a[3]), "r"(b[0]), "r"(b[1]));
}
__device__ __forceinline__ int PD(int a, int c) { return a * 7 - (a * (a + 1)) / 2 + c; }

// ---------------------------------------------------------------------------
// prep: blocks [0,96) mask-channel active flags; blocks >=96 zero accumulators
// ---------------------------------------------------------------------------
#define ZBLK 224
__global__ void prep_kernel(const float* __restrict__ masks) {
    int blk = blockIdx.x;
    if (blk < BATCH * NMASK) {
        const float* m = masks + (size_t)blk * HW;
        float s = 0.f;
        for (int i = threadIdx.x; i < HW; i += blockDim.x) s += m[i];
        __shared__ float sh[256];
        sh[threadIdx.x] = s;
        __syncthreads();
        for (int o = 128; o > 0; o >>= 1) {
            if (threadIdx.x < o) sh[threadIdx.x] += sh[threadIdx.x + o];
            __syncthreads();
        }
        if (threadIdx.x == 0) g_active[blk] = (sh[0] > 0.f) ? 1 : 0;
    } else {
        int i = (blk - BATCH * NMASK) * 256 + threadIdx.x;
        if (i < BATCH * HW) { g_S[i] = 0.f; g_P[i] = 0.f; g_C[i] = 0.f; }
        if (i < BATCH * NLBL * DIM) ((float*)g_label_sums)[i] = 0.f;
        if (i < BATCH * NLBL) { ((float*)g_cnt)[i] = 0.f; ((float*)g_q)[i] = 0.f; }
    }
}

// ---------------------------------------------------------------------------
// labels
// ---------------------------------------------------------------------------
__global__ void labels_kernel(const float* __restrict__ masks) {
    int idx = blockIdx.x * blockDim.x + threadIdx.x;
    if (idx >= BATCH * HW) return;
    int b = idx / HW, n = idx - b * HW;
    const float* mb = masks + (size_t)b * NMASK * HW;
    int lbl = 0;
#pragma unroll
    for (int m = 0; m < NMASK; m++) {
        if (mb[(size_t)m * HW + n] > 0.5f && g_active[b * NMASK + m]) lbl = m + 1;
    }
    g_labels[idx] = lbl;
}

// ---------------------------------------------------------------------------
// rn2 + fp32 -> fp16 conversion. One warp per pixel.
// ---------------------------------------------------------------------------
__global__ void rn2_cvt_kernel(const float* __restrict__ emb) {
    int w = (blockIdx.x * blockDim.x + threadIdx.x) >> 5;
    int lane = threadIdx.x & 31;
    if (w >= BATCH * HW) return;
    const float4* src = (const float4*)(emb + (size_t)w * DIM) + lane * 4;
    __half hh[16];
    float s = 0.f;
#pragma unroll
    for (int k = 0; k < 4; k++) {
        float4 v = src[k];
        float vv[4] = {v.x, v.y, v.z, v.w};
#pragma unroll
        for (int e = 0; e < 4; e++) {
            float f = vv[e];
            s += f * f;
            hh[k * 4 + e] = __float2half(f);
        }
    }
#pragma unroll
    for (int o = 16; o > 0; o >>= 1) s += __shfl_xor_sync(0xffffffffu, s, o);
    if (lane == 0) g_rn2[w] = s;
    uint4* dh = (uint4*)(g_h + (size_t)w * DIM + lane * 16);
    dh[0] = ((uint4*)hh)[0]; dh[1] = ((uint4*)hh)[1];
}

// ---------------------------------------------------------------------------
// supcon Gram tile via mma.sync fp16 (single product, fp32 accum).
// 128x128 tile per block (symmetric: ct>=rt). K=512 in 8 chunks of 64,
// double-buffered cp.async (2x32KB), register epilogue, symmetric scatter.
// ---------------------------------------------------------------------------
__global__ __launch_bounds__(256, 2) void supcon_mma_kernel() {
    extern __shared__ char smem[];
    uint32_t sb = smem_u32(smem);
    int tid = threadIdx.x;
    int wid = tid >> 5, lane = tid & 31;
    int wr = wid >> 1, wc = wid & 1;
    int b = blockIdx.y;
    int idx = blockIdx.x, rt = 0;
    while (idx >= CTILES - rt) { idx -= CTILES - rt; rt++; }
    int ct = rt + idx;
    bool diag = (ct == rt);
    int row0 = rt * 128, col0 = ct * 128;

    int* lrow = (int*)(smem + SM_LROW);
    int* lcol = (int*)(smem + SM_LCOL);
    float* rowS = (float*)(smem + SM_ROWS);
    float* rowP = (float*)(smem + SM_ROWP);
    float* rowC = (float*)(smem + SM_ROWC);
    float* colS = (float*)(smem + SM_COLS);
    float* colP = (float*)(smem + SM_COLP);
    float* colC = (float*)(smem + SM_COLC);
    if (tid < 128) {
        int r = row0 + tid, c = col0 + tid;
        lrow[tid] = (r < HW) ? g_labels[b * HW + r] : -1;
        lcol[tid] = (c < HW) ? g_labels[b * HW + c] : -2;
        rowS[tid] = 0.f; rowP[tid] = 0.f; rowC[tid] = 0.f;
        colS[tid] = 0.f; colP[tid] = 0.f; colC[tid] = 0.f;
    }

    const __half* bp = g_h + (size_t)b * HW * DIM;

    // ---- cp.async stage loader: 2 mats x 16KB, 128B rows, xor swizzle ----
    auto load_stage = [&](int c, int p) {
        uint32_t dst_base = sb + SM_BUF + p * STAGESZ;
#pragma unroll
        for (int it = 0; it < 8; it++) {
            int mat = it >> 2;                   // 0 = A, 1 = B
            int idxm = tid + 256 * (it & 3);     // 0..1023
            int row = idxm >> 3, seg = idxm & 7;
            int grow = ((mat == 0) ? row0 : col0) + row;
            uint32_t sz = (grow < HW) ? 16u : 0u;
            int gcl = (grow < HW) ? grow : 0;
            const __half* src = bp + (size_t)gcl * DIM + c * 64 + seg * 8;
            uint32_t dst = dst_base + mat * MATSZ + row * 128 +
                           (((uint32_t)(seg * 16)) ^ (((uint32_t)row & 7u) << 4));
            asm volatile("cp.async.cg.shared.global [%0], [%1], 16, %2;"
                         :: "r"(dst), "l"(src), "r"(sz) : "memory");
        }
        asm volatile("cp.async.commit_group;" ::: "memory");
    };

    // fragment address components (128B rows, swizzle mask (row&7)<<4)
    int a_r = wr * 32 + (lane & 15);
    uint32_t a_xm = (((uint32_t)lane) & 7u) << 4;
    uint32_t a_kb = (uint32_t)((lane >> 4) * 16);
    int b_n = wc * 64 + ((lane >> 4) & 1) * 8 + (lane & 7);
    uint32_t b_xm = (((uint32_t)lane) & 7u) << 4;
    uint32_t b_kb = (uint32_t)(((lane >> 3) & 1) * 16);

    float acc[2][8][4];
#pragma unroll
    for (int mt = 0; mt < 2; mt++)
#pragma unroll
        for (int nt = 0; nt < 8; nt++)
#pragma unroll
            for (int e = 0; e < 4; e++) acc[mt][nt][e] = 0.f;

    load_stage(0, 0);
    for (int c = 0; c < 8; c++) {
        int p = c & 1;
        if (c + 1 < 8) {
            load_stage(c + 1, p ^ 1);
            asm volatile("cp.async.wait_group 1;" ::: "memory");
        } else {
            asm volatile("cp.async.wait_group 0;" ::: "memory");
        }
        __syncthreads();
        uint32_t stg = sb + SM_BUF + p * STAGESZ;
#pragma unroll
        for (int ks = 0; ks < 4; ks++) {
            uint32_t ka = (((uint32_t)(ks * 32)) + a_kb) ^ a_xm;
            uint32_t ah[2][4];
#pragma unroll
            for (int mt = 0; mt < 2; mt++) {
                uint32_t ad = stg + (uint32_t)((a_r + mt * 16) * 128) + ka;
                ldsm4(ah[mt], ad);
            }
            uint32_t kb2 = (((uint32_t)(ks * 32)) + b_kb) ^ b_xm;
#pragma unroll
            for (int ntp = 0; ntp < 4; ntp++) {
                uint32_t bh4[4];
                uint32_t bd = stg + MATSZ + (uint32_t)((b_n + ntp * 16) * 128) + kb2;
                ldsm4(bh4, bd);
#pragma unroll
                for (int mt = 0; mt < 2; mt++) {
                    mma_f16(acc[mt][2 * ntp],     ah[mt], &bh4[0]);
                    mma_f16(acc[mt][2 * ntp + 1], ah[mt], &bh4[2]);
                }
            }
        }
        __syncthreads();
    }

    // ---- register epilogue ----
    int lr4 = lane >> 2;
    float S[4], P[4], C4[4];
    int rloc[4], rl[4];
#pragma unroll
    for (int q = 0; q < 4; q++) {
        rloc[q] = wr * 32 + (q >> 1) * 16 + (q & 1) * 8 + lr4;
        rl[q] = lrow[rloc[q]];
        S[q] = P[q] = C4[q] = 0.f;
    }
#pragma unroll
    for (int mt = 0; mt < 2; mt++)
#pragma unroll
        for (int nt = 0; nt < 8; nt++) {
            int cl0 = wc * 64 + nt * 8 + (lane & 3) * 2;
            int c0l = lcol[cl0], c1l = lcol[cl0 + 1];
            int cg0 = col0 + cl0, cg1 = cg0 + 1;
            float Sc0 = 0.f, Pc0 = 0.f, Cc0 = 0.f;
            float Sc1 = 0.f, Pc1 = 0.f, Cc1 = 0.f;
#pragma unroll
            for (int h = 0; h < 2; h++) {
                int q = mt * 2 + h;
                int rg = row0 + rloc[q];
                float d0 = acc[mt][nt][h * 2 + 0], d1 = acc[mt][nt][h * 2 + 1];
                float x0 = (d0 - 1.0f) * INV_T, x1 = (d1 - 1.0f) * INV_T;
                float e0 = __expf(x0), e1 = __expf(x1);
                if (rg < HW && cg0 < HW && cg0 != rg) {
                    S[q] += e0; Sc0 += e0;
                    if (c0l == rl[q]) { P[q] += x0; C4[q] += 1.f; Pc0 += x0; Cc0 += 1.f; }
                }
                if (rg < HW && cg1 < HW && cg1 != rg) {
                    S[q] += e1; Sc1 += e1;
                    if (c1l == rl[q]) { P[q] += x1; C4[q] += 1.f; Pc1 += x1; Cc1 += 1.f; }
                }
            }
            if (!diag) {
#pragma unroll
                for (int o = 4; o <= 16; o <<= 1) {
                    Sc0 += __shfl_xor_sync(0xffffffffu, Sc0, o);
                    Pc0 += __shfl_xor_sync(0xffffffffu, Pc0, o);
                    Cc0 += __shfl_xor_sync(0xffffffffu, Cc0, o);
                    Sc1 += __shfl_xor_sync(0xffffffffu, Sc1, o);
                    Pc1 += __shfl_xor_sync(0xffffffffu, Pc1, o);
                    Cc1 += __shfl_xor_sync(0xffffffffu, Cc1, o);
                }
                if (lane < 4) {
                    atomicAdd(&colS[cl0], Sc0);     atomicAdd(&colS[cl0 + 1], Sc1);
                    atomicAdd(&colP[cl0], Pc0);     atomicAdd(&colP[cl0 + 1], Pc1);
                    atomicAdd(&colC[cl0], Cc0);     atomicAdd(&colC[cl0 + 1], Cc1);
                }
            }
        }
#pragma unroll
    for (int q = 0; q < 4; q++) {
#pragma unroll
        for (int o = 1; o <= 2; o <<= 1) {
            S[q]  += __shfl_xor_sync(0xffffffffu, S[q], o);
            P[q]  += __shfl_xor_sync(0xffffffffu, P[q], o);
            C4[q] += __shfl_xor_sync(0xffffffffu, C4[q], o);
        }
    }
    if ((lane & 3) == 0) {
#pragma unroll
        for (int q = 0; q < 4; q++) {
            atomicAdd(&rowS[rloc[q]], S[q]);
            atomicAdd(&rowP[rloc[q]], P[q]);
            atomicAdd(&rowC[rloc[q]], C4[q]);
        }
    }
    __syncthreads();
    if (tid < 128) {
        int rg = row0 + tid;
        if (rg < HW) {
            atomicAdd(&g_S[b * HW + rg], rowS[tid]);
            atomicAdd(&g_P[b * HW + rg], rowP[tid]);
            atomicAdd(&g_C[b * HW + rg], rowC[tid]);
        }
    } else if (!diag) {
        int j = tid - 128;
        int cg = col0 + j;
        if (cg < HW) {
            atomicAdd(&g_S[b * HW + cg], colS[j]);
            atomicAdd(&g_P[b * HW + cg], colP[j]);
            atomicAdd(&g_C[b * HW + cg], colC[j]);
        }
    }
}

// ---------------------------------------------------------------------------
// centroids: parallel over (chunk, image). Each block sums 33 rows.
// ---------------------------------------------------------------------------
__global__ void centroid_kernel(const float* __restrict__ emb) {
    int chunk = blockIdx.x;
    int b = blockIdx.y;
    int t = threadIdx.x;
    int r0 = chunk * 33, r1 = r0 + 33;
    const float* fb = emb + (size_t)b * HW * DIM;
    float acc[NLBL];
#pragma unroll
    for (int l = 0; l < NLBL; l++) acc[l] = 0.f;
    for (int n = r0; n < r1; n++) {
        int lbl = g_labels[b * HW + n];
        float v = fb[(size_t)n * DIM + t];
#pragma unroll
        for (int l = 0; l < NLBL; l++) acc[l] += (lbl == l) ? v : 0.f;
    }
#pragma unroll
    for (int l = 0; l < NLBL; l++)
        if (acc[l] != 0.f) atomicAdd(&g_label_sums[b][l][t], acc[l]);
    if (t < NLBL) {
        float c = 0.f, q = 0.f;
        for (int n = r0; n < r1; n++) {
            if (g_labels[b * HW + n] == t) { c += 1.f; q += g_rn2[b * HW + n]; }
        }
        if (c != 0.f) { atomicAdd(&g_cnt[b][t], c); atomicAdd(&g_q[b][t], q); }
    }
}

// ---------------------------------------------------------------------------
// per-row supcon loss + per-image reduction
// ---------------------------------------------------------------------------
__global__ void supcon_row_kernel() {
    int b = blockIdx.x;
    int t = threadIdx.x;
    float s = 0.f, n = 0.f;
    for (int r = t; r < HW; r += 256) {
        float c = g_C[b * HW + r];
        if (c > 0.f) {
            s += -((g_P[b * HW + r] - c * logf(g_S[b * HW + r] + 1e-6f)) / c);
            n += 1.f;
        }
    }
    __shared__ float sS[256], sN[256];
    sS[t] = s; sN[t] = n;
    __syncthreads();
    for (int o = 128; o > 0; o >>= 1) {
        if (t < o) { sS[t] += sS[t + o]; sN[t] += sN[t + o]; }
        __syncthreads();
    }
    if (t == 0) { g_supcon_sum[b] = sS[0]; g_anchor_cnt[b] = sN[0]; }
}

// ---------------------------------------------------------------------------
// pairdot: per-image, 512 threads (thread = dim). 28 centroid pair-dots
// (incl self-norms) + ||mean_all||^2.
// ---------------------------------------------------------------------------
__global__ void pairdot_kernel() {
    int b = blockIdx.x;
    int t = threadIdx.x;
    int lane = t & 31;
    float inv[NLBL];
#pragma unroll
    for (int l = 0; l < NLBL; l++) inv[l] = 1.f / fmaxf(g_cnt[b][l], 1.f);
    float raw[NLBL], m[NLBL];
    float sall = 0.f;
#pragma unroll
    for (int l = 0; l < NLBL; l++) {
        raw[l] = g_label_sums[b][l][t];
        m[l] = raw[l] * inv[l];
        sall += raw[l];
    }
    sall *= (1.f / (float)HW);
    float part[NPD];
    int k = 0;
#pragma unroll
    for (int l1 = 0; l1 < NLBL; l1++)
#pragma unroll
        for (int l2 = l1; l2 < NLBL; l2++) part[k++] = m[l1] * m[l2];
    part[28] = sall * sall;
#pragma unroll
    for (int i = 0; i < NPD; i++)
#pragma unroll
        for (int o = 16; o > 0; o >>= 1) part[i] += __shfl_xor_sync(0xffffffffu, part[i], o);
    __shared__ float acc[NPD];
    if (t < NPD) acc[t] = 0.f;
    __syncthreads();
    if (lane == 0) {
#pragma unroll
        for (int i = 0; i < NPD; i++) atomicAdd(&acc[i], part[i]);
    }
    __syncthreads();
    if (t < NPD) g_pd[b][t] = acc[t];
}

// ---------------------------------------------------------------------------
// finalize: pure scalar math from precomputed reductions
// ---------------------------------------------------------------------------
__global__ void finalize_kernel(const float* __restrict__ is_forged, float* __restrict__ out) {
    __shared__ float sc[BATCH], scv[BATCH], sp[BATCH], spv[BATCH], un[BATCH], unv[BATCH];
    int t = threadIdx.x;
    if (t < BATCH) {
        int b = t;
        float na = g_anchor_cnt[b];
        float supcon = g_supcon_sum[b] / fmaxf(na, 1.f);
        float supcon_valid = (na > 0.f) ? 1.f : 0.f;

        float pd[NPD];
#pragma unroll
        for (int i = 0; i < NPD; i++) pd[i] = g_pd[b][i];
        float cnt[NLBL], cn[NLBL], inv[NLBL];
#pragma unroll
        for (int l = 0; l < NLBL; l++) {
            cnt[l] = g_cnt[b][l];
            inv[l] = 1.f / fmaxf(cnt[l], 1.f);
            cn[l] = pd[PD(l, l)];
        }
        float terms = 0.f, npairs = 0.f;
        int npresent = 0;
#pragma unroll
        for (int l = 0; l < NLBL; l++) if (cnt[l] > 0.f) npresent++;
#pragma unroll
        for (int l1 = 0; l1 < NLBL; l1++)
#pragma unroll
            for (int l2 = l1 + 1; l2 < NLBL; l2++) {
                if (cnt[l1] > 0.f && cnt[l2] > 0.f) {
                    float sq = cn[l1] + cn[l2] - 2.f * pd[PD(l1, l2)];
                    float dd = sqrtf(fmaxf(sq, 0.f));
                    terms += fmaxf(SEPM - dd, 0.f);
                    npairs += 1.f;
                }
            }
        float sep = terms / fmaxf(npairs, 1.f);
        float sep_valid = (npresent >= 2) ? 1.f : 0.f;

        float uni, univ;
        if (is_forged[b] >= 0.5f) {
            float inst = 0.f, nl = 0.f;
#pragma unroll
            for (int l = 0; l < NLBL; l++) {
                float var = g_q[b][l] * inv[l] - cn[l];
                if (cnt[l] >= 2.f && var > UNITH) { inst += var - UNITH; nl += 1.f; }
            }
            uni = inst / fmaxf(nl, 1.f);
            univ = (nl > 0.f) ? 1.f : 0.f;
        } else {
            float qall = 0.f;
#pragma unroll
            for (int l = 0; l < NLBL; l++) qall += g_q[b][l];
            float var_all = qall * (1.f / (float)HW) - pd[28];
            uni = (var_all > UNITH) ? (var_all - UNITH) : 0.f;
            univ = (var_all > UNITH) ? 1.f : 0.f;
        }

        sc[b] = supcon * supcon_valid; scv[b] = supcon_valid;
        sp[b] = sep * sep_valid;       spv[b] = sep_valid;
        un[b] = uni * univ;            unv[b] = univ;
    }
    __syncthreads();
    if (t == 0) {
        float a = 0.f, av = 0.f, s2 = 0.f, sv = 0.f, u = 0.f, uv = 0.f;
        for (int b = 0; b < BATCH; b++) {
            a += sc[b]; av += scv[b];
            s2 += sp[b]; sv += spv[b];
            u += un[b]; uv += unv[b];
        }
        float supcon = (av > 0.f) ? a / fmaxf(av, 1.f) : 0.f;
        float sep = (sv > 0.f) ? s2 / fmaxf(sv, 1.f) : 0.f;
        float uni = (uv > 0.f) ? u / fmaxf(uv, 1.f) : 0.f;
        out[0] = 1.0f * supcon + 0.5f * sep + 0.5f * uni;
    }
}

// ---------------------------------------------------------------------------
extern "C" void kernel_launch(void* const* d_in, const int* in_sizes, int n_in,
                              void* d_out, int out_size) {
    const float* emb   = (const float*)d_in[0];   // (16,33,33,512) f32
    const float* masks = (const float*)d_in[1];   // (16,6,33,33) f32
    const float* isf   = (const float*)d_in[2];   // (16,) f32
    float* out = (float*)d_out;

    cudaFuncSetAttribute(supcon_mma_kernel,
                         cudaFuncAttributeMaxDynamicSharedMemorySize, SM_TOTAL);

    prep_kernel<<<BATCH * NMASK + ZBLK, 256>>>(masks);                 // 0
    labels_kernel<<<(BATCH * HW + 255) / 256, 256>>>(masks);           // 1
    rn2_cvt_kernel<<<(BATCH * HW * 32 + 255) / 256, 256>>>(emb);       // 2
    supcon_mma_kernel<<<dim3(NTILEPAIRS, BATCH), 256, SM_TOTAL>>>();   // 3 (ncu slot)
    centroid_kernel<<<dim3(CCH, BATCH), DIM>>>(emb);                   // 4
    supcon_row_kernel<<<BATCH, 256>>>();                               // 5
    pairdot_kernel<<<BATCH, DIM>>>();                                  // 6
    finalize_kernel<<<1, 32>>>(isf, out);                              // 7
}

// round 10
// speedup vs baseline: 7.5231x; 1.1165x over previous
#include <cuda_runtime.h>
#include <cuda_fp16.h>
#include <cstdint>
#include <math.h>

#define BATCH 16
#define NMASK 6
#define HW 1089
#define DIM 512
#define NLBL 7
#define INV_T (1.0f/0.07f)
#define SEPM 2.0f
#define UNITH 0.1f

#define CTILES 9          // ceil(1089/128)
#define NTILEPAIRS 45     // CTILES*(CTILES+1)/2
#define CCH 33            // centroid chunks (33 rows each)
#define NPD 29            // 28 pair-dots + ||mean_all||^2

// ---- smem layout for supcon_mma (dynamic) ----
#define SM_LROW 0                 // 128 int
#define SM_LCOL 512
#define SM_ROWS 1024
#define SM_ROWP 1536
#define SM_ROWC 2048
#define SM_COLS 2560
#define SM_COLP 3072
#define SM_COLC 3584
#define SM_BUF  4096
#define MATSZ   16384             // 128 rows x 64 fp16 (128B/row)
#define STAGESZ (2*MATSZ)         // A,B = 32KB
#define NSTAGE  3
#define SM_TOTAL (SM_BUF + NSTAGE*STAGESZ)   // 102400 -> 2 CTAs/SM (reg-capped)

// ---- scratch (device globals: allocation-free) ----
__device__ float g_label_sums[BATCH][NLBL][DIM];
__device__ float g_cnt[BATCH][NLBL];
__device__ float g_q[BATCH][NLBL];
__device__ float g_supcon_sum[BATCH];
__device__ float g_anchor_cnt[BATCH];
__device__ float g_pd[BATCH][NPD];
__device__ int   g_active[BATCH * NMASK];
__device__ int   g_labels[BATCH * HW];
__device__ float g_rn2[BATCH * HW];
__device__ float g_S[BATCH * HW];
__device__ float g_P[BATCH * HW];
__device__ float g_C[BATCH * HW];
__device__ __align__(16) __half g_h[(size_t)BATCH * HW * DIM];

// ================= helpers =================
__device__ __forceinline__ uint32_t smem_u32(const void* p) {
    uint32_t a;
    asm("{ .reg .u64 t; cvta.to.shared.u64 t, %1; cvt.u32.u64 %0, t; }" : "=r"(a) : "l"(p));
    return a;
}
__device__ __forceinline__ void ldsm4(uint32_t* r, uint32_t addr) {
    asm volatile("ldmatrix.sync.aligned.m8n8.x4.shared.b16 {%0,%1,%2,%3}, [%4];"
                 : "=r"(r[0]), "=r"(r[1]), "=r"(r[2]), "=r"(r[3]) : "r"(addr));
}
__device__ __forceinline__ void mma_f16(float* c, const uint32_t* a, const uint32_t* b) {
    asm volatile("mma.sync.aligned.m16n8k16.row.col.f32.f16.f16.f32 "
                 "{%0,%1,%2,%3}, {%4,%5,%6,%7}, {%8,%9}, {%0,%1,%2,%3};"
                 : "+f"(c[0]), "+f"(c[1]), "+f"(c[2]), "+f"(c[3])
                 : "r"(a[0]), "r"(a[1]), "r"(a[2]), "r"(a[3]), "r"(b[0]), "r"(b[1]));
}
__device__ __forceinline__ int PD(int a, int c) { return a * 7 - (a * (a + 1)) / 2 + c; }

// ---------------------------------------------------------------------------
// prep: blocks [0,96) mask-channel active flags; blocks >=96 zero accumulators
// ---------------------------------------------------------------------------
#define ZBLK 224
__global__ void prep_kernel(const float* __restrict__ masks) {
    int blk = blockIdx.x;
    if (blk < BATCH * NMASK) {
        const float* m = masks + (size_t)blk * HW;
        float s = 0.f;
        for (int i = threadIdx.x; i < HW; i += blockDim.x) s += m[i];
        __shared__ float sh[256];
        sh[threadIdx.x] = s;
        __syncthreads();
        for (int o = 128; o > 0; o >>= 1) {
            if (threadIdx.x < o) sh[threadIdx.x] += sh[threadIdx.x + o];
            __syncthreads();
        }
        if (threadIdx.x == 0) g_active[blk] = (sh[0] > 0.f) ? 1 : 0;
    } else {
        int i = (blk - BATCH * NMASK) * 256 + threadIdx.x;
        if (i < BATCH * HW) { g_S[i] = 0.f; g_P[i] = 0.f; g_C[i] = 0.f; }
        if (i < BATCH * NLBL * DIM) ((float*)g_label_sums)[i] = 0.f;
        if (i < BATCH * NLBL) { ((float*)g_cnt)[i] = 0.f; ((float*)g_q)[i] = 0.f; }
    }
}

// ---------------------------------------------------------------------------
// labels
// ---------------------------------------------------------------------------
__global__ void labels_kernel(const float* __restrict__ masks) {
    int idx = blockIdx.x * blockDim.x + threadIdx.x;
    if (idx >= BATCH * HW) return;
    int b = idx / HW, n = idx - b * HW;
    const float* mb = masks + (size_t)b * NMASK * HW;
    int lbl = 0;
#pragma unroll
    for (int m = 0; m < NMASK; m++) {
        if (mb[(size_t)m * HW + n] > 0.5f && g_active[b * NMASK + m]) lbl = m + 1;
    }
    g_labels[idx] = lbl;
}

// ---------------------------------------------------------------------------
// rn2 + fp32 -> fp16 conversion. One warp per pixel.
// ---------------------------------------------------------------------------
__global__ void rn2_cvt_kernel(const float* __restrict__ emb) {
    int w = (blockIdx.x * blockDim.x + threadIdx.x) >> 5;
    int lane = threadIdx.x & 31;
    if (w >= BATCH * HW) return;
    const float4* src = (const float4*)(emb + (size_t)w * DIM) + lane * 4;
    __half hh[16];
    float s = 0.f;
#pragma unroll
    for (int k = 0; k < 4; k++) {
        float4 v = src[k];
        float vv[4] = {v.x, v.y, v.z, v.w};
#pragma unroll
        for (int e = 0; e < 4; e++) {
            float f = vv[e];
            s += f * f;
            hh[k * 4 + e] = __float2half(f);
        }
    }
#pragma unroll
    for (int o = 16; o > 0; o >>= 1) s += __shfl_xor_sync(0xffffffffu, s, o);
    if (lane == 0) g_rn2[w] = s;
    uint4* dh = (uint4*)(g_h + (size_t)w * DIM + lane * 16);
    dh[0] = ((uint4*)hh)[0]; dh[1] = ((uint4*)hh)[1];
}

// ---------------------------------------------------------------------------
// supcon Gram tile via mma.sync fp16 (single product, fp32 accum).
// 128x128 tile per block (symmetric: ct>=rt). K=512 in 8 chunks of 64,
// 3-stage cp.async pipeline with ONE __syncthreads per chunk,
// register epilogue with per-nt column reduction, symmetric scatter.
// ---------------------------------------------------------------------------
__global__ __launch_bounds__(256, 2) void supcon_mma_kernel() {
    extern __shared__ char smem[];
    uint32_t sb = smem_u32(smem);
    int tid = threadIdx.x;
    int wid = tid >> 5, lane = tid & 31;
    int wr = wid >> 1, wc = wid & 1;
    int b = blockIdx.y;
    int idx = blockIdx.x, rt = 0;
    while (idx >= CTILES - rt) { idx -= CTILES - rt; rt++; }
    int ct = rt + idx;
    bool diag = (ct == rt);
    int row0 = rt * 128, col0 = ct * 128;

    int* lrow = (int*)(smem + SM_LROW);
    int* lcol = (int*)(smem + SM_LCOL);
    float* rowS = (float*)(smem + SM_ROWS);
    float* rowP = (float*)(smem + SM_ROWP);
    float* rowC = (float*)(smem + SM_ROWC);
    float* colS = (float*)(smem + SM_COLS);
    float* colP = (float*)(smem + SM_COLP);
    float* colC = (float*)(smem + SM_COLC);
    if (tid < 128) {
        int r = row0 + tid, c = col0 + tid;
        lrow[tid] = (r < HW) ? g_labels[b * HW + r] : -1;
        lcol[tid] = (c < HW) ? g_labels[b * HW + c] : -2;
        rowS[tid] = 0.f; rowP[tid] = 0.f; rowC[tid] = 0.f;
        colS[tid] = 0.f; colP[tid] = 0.f; colC[tid] = 0.f;
    }

    const __half* bp = g_h + (size_t)b * HW * DIM;

    // ---- cp.async stage loader: 2 mats x 16KB, 128B rows, xor swizzle ----
    auto load_stage = [&](int c, int buf) {
        uint32_t dst_base = sb + SM_BUF + buf * STAGESZ;
#pragma unroll
        for (int it = 0; it < 8; it++) {
            int mat = it >> 2;                   // 0 = A, 1 = B
            int idxm = tid + 256 * (it & 3);     // 0..1023
            int row = idxm >> 3, seg = idxm & 7;
            int grow = ((mat == 0) ? row0 : col0) + row;
            uint32_t sz = (grow < HW) ? 16u : 0u;
            int gcl = (grow < HW) ? grow : 0;
            const __half* src = bp + (size_t)gcl * DIM + c * 64 + seg * 8;
            uint32_t dst = dst_base + mat * MATSZ + row * 128 +
                           (((uint32_t)(seg * 16)) ^ (((uint32_t)row & 7u) << 4));
            asm volatile("cp.async.cg.shared.global [%0], [%1], 16, %2;"
                         :: "r"(dst), "l"(src), "r"(sz) : "memory");
        }
        asm volatile("cp.async.commit_group;" ::: "memory");
    };

    // fragment address components (128B rows, swizzle mask (row&7)<<4)
    int a_r = wr * 32 + (lane & 15);
    uint32_t a_xm = (((uint32_t)lane) & 7u) << 4;
    uint32_t a_kb = (uint32_t)((lane >> 4) * 16);
    int b_n = wc * 64 + ((lane >> 4) & 1) * 8 + (lane & 7);
    uint32_t b_xm = (((uint32_t)lane) & 7u) << 4;
    uint32_t b_kb = (uint32_t)(((lane >> 3) & 1) * 16);

    float acc[2][8][4];
#pragma unroll
    for (int mt = 0; mt < 2; mt++)
#pragma unroll
        for (int nt = 0; nt < 8; nt++)
#pragma unroll
            for (int e = 0; e < 4; e++) acc[mt][nt][e] = 0.f;

    load_stage(0, 0);
    load_stage(1, 1);
    for (int c = 0; c < 8; c++) {
        // wait for chunk c: groups issued after c = min(1, 7-c)
        if (c < 7) asm volatile("cp.async.wait_group 1;" ::: "memory");
        else       asm volatile("cp.async.wait_group 0;" ::: "memory");
        __syncthreads();   // chunk c visible to all; all warps done computing c-1
        if (c + 2 < 8) load_stage(c + 2, (c + 2) % NSTAGE);  // buffer of c-1: safe
        uint32_t stg = sb + SM_BUF + (c % NSTAGE) * STAGESZ;
#pragma unroll
        for (int ks = 0; ks < 4; ks++) {
            uint32_t ka = (((uint32_t)(ks * 32)) + a_kb) ^ a_xm;
            uint32_t ah[2][4];
#pragma unroll
            for (int mt = 0; mt < 2; mt++) {
                uint32_t ad = stg + (uint32_t)((a_r + mt * 16) * 128) + ka;
                ldsm4(ah[mt], ad);
            }
            uint32_t kb2 = (((uint32_t)(ks * 32)) + b_kb) ^ b_xm;
#pragma unroll
            for (int ntp = 0; ntp < 4; ntp++) {
                uint32_t bh4[4];
                uint32_t bd = stg + MATSZ + (uint32_t)((b_n + ntp * 16) * 128) + kb2;
                ldsm4(bh4, bd);
#pragma unroll
                for (int mt = 0; mt < 2; mt++) {
                    mma_f16(acc[mt][2 * ntp],     ah[mt], &bh4[0]);
                    mma_f16(acc[mt][2 * ntp + 1], ah[mt], &bh4[2]);
                }
            }
        }
    }
    __syncthreads();   // last compute done before epilogue reuses nothing, but
                       // needed before smem col/row atomics ordering below

    // ---- register epilogue: rows via shfl(1,2); cols per-nt via shfl(4,8,16) ----
    int lr4 = lane >> 2;
    float S[4], P[4], C4[4];
    int rloc[4], rl[4];
#pragma unroll
    for (int q = 0; q < 4; q++) {
        rloc[q] = wr * 32 + (q >> 1) * 16 + (q & 1) * 8 + lr4;
        rl[q] = lrow[rloc[q]];
        S[q] = P[q] = C4[q] = 0.f;
    }
#pragma unroll
    for (int nt = 0; nt < 8; nt++) {
        int cl0 = wc * 64 + nt * 8 + (lane & 3) * 2;
        int c0l = lcol[cl0], c1l = lcol[cl0 + 1];
        int cg0 = col0 + cl0, cg1 = cg0 + 1;
        float Sc0 = 0.f, Pc0 = 0.f, Cc0 = 0.f;
        float Sc1 = 0.f, Pc1 = 0.f, Cc1 = 0.f;
#pragma unroll
        for (int mt = 0; mt < 2; mt++)
#pragma unroll
            for (int h = 0; h < 2; h++) {
                int q = mt * 2 + h;
                int rg = row0 + rloc[q];
                float d0 = acc[mt][nt][h * 2 + 0], d1 = acc[mt][nt][h * 2 + 1];
                float x0 = (d0 - 1.0f) * INV_T, x1 = (d1 - 1.0f) * INV_T;
                float e0 = __expf(x0), e1 = __expf(x1);
                if (rg < HW && cg0 < HW && cg0 != rg) {
                    S[q] += e0; Sc0 += e0;
                    if (c0l == rl[q]) { P[q] += x0; C4[q] += 1.f; Pc0 += x0; Cc0 += 1.f; }
                }
                if (rg < HW && cg1 < HW && cg1 != rg) {
                    S[q] += e1; Sc1 += e1;
                    if (c1l == rl[q]) { P[q] += x1; C4[q] += 1.f; Pc1 += x1; Cc1 += 1.f; }
                }
            }
        if (!diag) {
#pragma unroll
            for (int o = 4; o <= 16; o <<= 1) {
                Sc0 += __shfl_xor_sync(0xffffffffu, Sc0, o);
                Pc0 += __shfl_xor_sync(0xffffffffu, Pc0, o);
                Cc0 += __shfl_xor_sync(0xffffffffu, Cc0, o);
                Sc1 += __shfl_xor_sync(0xffffffffu, Sc1, o);
                Pc1 += __shfl_xor_sync(0xffffffffu, Pc1, o);
                Cc1 += __shfl_xor_sync(0xffffffffu, Cc1, o);
            }
            if (lane < 4) {
                atomicAdd(&colS[cl0], Sc0);     atomicAdd(&colS[cl0 + 1], Sc1);
                atomicAdd(&colP[cl0], Pc0);     atomicAdd(&colP[cl0 + 1], Pc1);
                atomicAdd(&colC[cl0], Cc0);     atomicAdd(&colC[cl0 + 1], Cc1);
            }
        }
    }
#pragma unroll
    for (int q = 0; q < 4; q++) {
#pragma unroll
        for (int o = 1; o <= 2; o <<= 1) {
            S[q]  += __shfl_xor_sync(0xffffffffu, S[q], o);
            P[q]  += __shfl_xor_sync(0xffffffffu, P[q], o);
            C4[q] += __shfl_xor_sync(0xffffffffu, C4[q], o);
        }
    }
    if ((lane & 3) == 0) {
#pragma unroll
        for (int q = 0; q < 4; q++) {
            atomicAdd(&rowS[rloc[q]], S[q]);
            atomicAdd(&rowP[rloc[q]], P[q]);
            atomicAdd(&rowC[rloc[q]], C4[q]);
        }
    }
    __syncthreads();
    if (tid < 128) {
        int rg = row0 + tid;
        if (rg < HW) {
            atomicAdd(&g_S[b * HW + rg], rowS[tid]);
            atomicAdd(&g_P[b * HW + rg], rowP[tid]);
            atomicAdd(&g_C[b * HW + rg], rowC[tid]);
        }
    } else if (!diag) {
        int j = tid - 128;
        int cg = col0 + j;
        if (cg < HW) {
            atomicAdd(&g_S[b * HW + cg], colS[j]);
            atomicAdd(&g_P[b * HW + cg], colP[j]);
            atomicAdd(&g_C[b * HW + cg], colC[j]);
        }
    }
}

// ---------------------------------------------------------------------------
// centroids: parallel over (chunk, image), reads the fp16 copy (half bytes).
// ---------------------------------------------------------------------------
__global__ void centroid_kernel() {
    int chunk = blockIdx.x;
    int b = blockIdx.y;
    int t = threadIdx.x;
    int r0 = chunk * 33, r1 = r0 + 33;
    const __half* fb = g_h + (size_t)b * HW * DIM;
    float acc[NLBL];
#pragma unroll
    for (int l = 0; l < NLBL; l++) acc[l] = 0.f;
#pragma unroll 3
    for (int n = r0; n < r1; n++) {
        int lbl = g_labels[b * HW + n];
        float v = __half2float(fb[(size_t)n * DIM + t]);
#pragma unroll
        for (int l = 0; l < NLBL; l++) acc[l] += (lbl == l) ? v : 0.f;
    }
#pragma unroll
    for (int l = 0; l < NLBL; l++)
        if (acc[l] != 0.f) atomicAdd(&g_label_sums[b][l][t], acc[l]);
    if (t < NLBL) {
        float c = 0.f, q = 0.f;
        for (int n = r0; n < r1; n++) {
            if (g_labels[b * HW + n] == t) { c += 1.f; q += g_rn2[b * HW + n]; }
        }
        if (c != 0.f) { atomicAdd(&g_cnt[b][t], c); atomicAdd(&g_q[b][t], q); }
    }
}

// ---------------------------------------------------------------------------
// merged: blocks [0,16) per-row supcon loss; blocks [16,32) pair-dots.
// ---------------------------------------------------------------------------
__global__ void rowpd_kernel() {
    int t = threadIdx.x;
    if (blockIdx.x < BATCH) {
        int b = blockIdx.x;
        float s = 0.f, n = 0.f;
        for (int r = t; r < HW; r += 512) {
            float c = g_C[b * HW + r];
            if (c > 0.f) {
                s += -((g_P[b * HW + r] - c * logf(g_S[b * HW + r] + 1e-6f)) / c);
                n += 1.f;
            }
        }
        __shared__ float sS[512], sN[512];
        sS[t] = s; sN[t] = n;
        __syncthreads();
        for (int o = 256; o > 0; o >>= 1) {
            if (t < o) { sS[t] += sS[t + o]; sN[t] += sN[t + o]; }
            __syncthreads();
        }
        if (t == 0) { g_supcon_sum[b] = sS[0]; g_anchor_cnt[b] = sN[0]; }
    } else {
        int b = blockIdx.x - BATCH;
        int lane = t & 31;
        float inv[NLBL];
#pragma unroll
        for (int l = 0; l < NLBL; l++) inv[l] = 1.f / fmaxf(g_cnt[b][l], 1.f);
        float raw[NLBL], m[NLBL];
        float sall = 0.f;
#pragma unroll
        for (int l = 0; l < NLBL; l++) {
            raw[l] = g_label_sums[b][l][t];
            m[l] = raw[l] * inv[l];
            sall += raw[l];
        }
        sall *= (1.f / (float)HW);
        float part[NPD];
        int k = 0;
#pragma unroll
        for (int l1 = 0; l1 < NLBL; l1++)
#pragma unroll
            for (int l2 = l1; l2 < NLBL; l2++) part[k++] = m[l1] * m[l2];
        part[28] = sall * sall;
#pragma unroll
        for (int i = 0; i < NPD; i++)
#pragma unroll
            for (int o = 16; o > 0; o >>= 1) part[i] += __shfl_xor_sync(0xffffffffu, part[i], o);
        __shared__ float acc[NPD];
        if (t < NPD) acc[t] = 0.f;
        __syncthreads();
        if (lane == 0) {
#pragma unroll
            for (int i = 0; i < NPD; i++) atomicAdd(&acc[i], part[i]);
        }
        __syncthreads();
        if (t < NPD) g_pd[b][t] = acc[t];
    }
}

// ---------------------------------------------------------------------------
// finalize: pure scalar math from precomputed reductions
// ---------------------------------------------------------------------------
__global__ void finalize_kernel(const float* __restrict__ is_forged, float* __restrict__ out) {
    __shared__ float sc[BATCH], scv[BATCH], sp[BATCH], spv[BATCH], un[BATCH], unv[BATCH];
    int t = threadIdx.x;
    if (t < BATCH) {
        int b = t;
        float na = g_anchor_cnt[b];
        float supcon = g_supcon_sum[b] / fmaxf(na, 1.f);
        float supcon_valid = (na > 0.f) ? 1.f : 0.f;

        float pd[NPD];
#pragma unroll
        for (int i = 0; i < NPD; i++) pd[i] = g_pd[b][i];
        float cnt[NLBL], cn[NLBL], inv[NLBL];
#pragma unroll
        for (int l = 0; l < NLBL; l++) {
            cnt[l] = g_cnt[b][l];
            inv[l] = 1.f / fmaxf(cnt[l], 1.f);
            cn[l] = pd[PD(l, l)];
        }
        float terms = 0.f, npairs = 0.f;
        int npresent = 0;
#pragma unroll
        for (int l = 0; l < NLBL; l++) if (cnt[l] > 0.f) npresent++;
#pragma unroll
        for (int l1 = 0; l1 < NLBL; l1++)
#pragma unroll
            for (int l2 = l1 + 1; l2 < NLBL; l2++) {
                if (cnt[l1] > 0.f && cnt[l2] > 0.f) {
                    float sq = cn[l1] + cn[l2] - 2.f * pd[PD(l1, l2)];
                    float dd = sqrtf(fmaxf(sq, 0.f));
                    terms += fmaxf(SEPM - dd, 0.f);
                    npairs += 1.f;
                }
            }
        float sep = terms / fmaxf(npairs, 1.f);
        float sep_valid = (npresent >= 2) ? 1.f : 0.f;

        float uni, univ;
        if (is_forged[b] >= 0.5f) {
            float inst = 0.f, nl = 0.f;
#pragma unroll
            for (int l = 0; l < NLBL; l++) {
                float var = g_q[b][l] * inv[l] - cn[l];
                if (cnt[l] >= 2.f && var > UNITH) { inst += var - UNITH; nl += 1.f; }
            }
            uni = inst / fmaxf(nl, 1.f);
            univ = (nl > 0.f) ? 1.f : 0.f;
        } else {
            float qall = 0.f;
#pragma unroll
            for (int l = 0; l < NLBL; l++) qall += g_q[b][l];
            float var_all = qall * (1.f / (float)HW) - pd[28];
            uni = (var_all > UNITH) ? (var_all - UNITH) : 0.f;
            univ = (var_all > UNITH) ? 1.f : 0.f;
        }

        sc[b] = supcon * supcon_valid; scv[b] = supcon_valid;
        sp[b] = sep * sep_valid;       spv[b] = sep_valid;
        un[b] = uni * univ;            unv[b] = univ;
    }
    __syncthreads();
    if (t == 0) {
        float a = 0.f, av = 0.f, s2 = 0.f, sv = 0.f, u = 0.f, uv = 0.f;
        for (int b = 0; b < BATCH; b++) {
            a += sc[b]; av += scv[b];
            s2 += sp[b]; sv += spv[b];
            u += un[b]; uv += unv[b];
        }
        float supcon = (av > 0.f) ? a / fmaxf(av, 1.f) : 0.f;
        float sep = (sv > 0.f) ? s2 / fmaxf(sv, 1.f) : 0.f;
        float uni = (uv > 0.f) ? u / fmaxf(uv, 1.f) : 0.f;
        out[0] = 1.0f * supcon + 0.5f * sep + 0.5f * uni;
    }
}

// ---------------------------------------------------------------------------
extern "C" void kernel_launch(void* const* d_in, const int* in_sizes, int n_in,
                              void* d_out, int out_size) {
    const float* emb   = (const float*)d_in[0];   // (16,33,33,512) f32
    const float* masks = (const float*)d_in[1];   // (16,6,33,33) f32
    const float* isf   = (const float*)d_in[2];   // (16,) f32
    float* out = (float*)d_out;

    cudaFuncSetAttribute(supcon_mma_kernel,
                         cudaFuncAttributeMaxDynamicSharedMemorySize, SM_TOTAL);

    prep_kernel<<<BATCH * NMASK + ZBLK, 256>>>(masks);                 // 0
    labels_kernel<<<(BATCH * HW + 255) / 256, 256>>>(masks);           // 1
    rn2_cvt_kernel<<<(BATCH * HW * 32 + 255) / 256, 256>>>(emb);       // 2
    supcon_mma_kernel<<<dim3(NTILEPAIRS, BATCH), 256, SM_TOTAL>>>();   // 3 (ncu slot)
    centroid_kernel<<<dim3(CCH, BATCH), DIM>>>();                      // 4
    rowpd_kernel<<<2 * BATCH, 512>>>();                                // 5
    finalize_kernel<<<1, 32>>>(isf, out);                              // 6
}

// round 11
// speedup vs baseline: 7.7986x; 1.0366x over previous
#include <cuda_runtime.h>
#include <cuda_fp16.h>
#include <cstdint>
#include <math.h>

#define BATCH 16
#define NMASK 6
#define HW 1089
#define DIM 512
#define NLBL 7
#define INV_T (1.0f/0.07f)
#define SEPM 2.0f
#define UNITH 0.1f

#define CTILES 9          // ceil(1089/128)
#define NTILEPAIRS 45     // CTILES*(CTILES+1)/2
#define CCH 33            // centroid chunks (33 rows each)
#define NPD 29            // 28 pair-dots + ||mean_all||^2

// ---- smem layout for supcon_mma (dynamic) ----
#define SM_LROW 0                 // 128 int
#define SM_LCOL 512
#define SM_ROWS 1024
#define SM_ROWP 1536
#define SM_ROWC 2048
#define SM_COLS 2560
#define SM_COLP 3072
#define SM_COLC 3584
#define SM_BUF  4096
#define MATSZ   16384             // 128 rows x 64 fp16 (128B/row)
#define STAGESZ (2*MATSZ)         // A,B = 32KB
#define NSTAGE  3
#define SM_TOTAL (SM_BUF + NSTAGE*STAGESZ)   // 102400 -> 2 CTAs/SM

// ---- scratch (device globals: allocation-free) ----
__device__ float g_label_sums[BATCH][NLBL][DIM];
__device__ float g_cnt[BATCH][NLBL];
__device__ float g_q[BATCH][NLBL];
__device__ float g_supcon_sum[BATCH];
__device__ float g_anchor_cnt[BATCH];
__device__ float g_pd[BATCH][NPD];
__device__ int   g_active[BATCH * NMASK];
__device__ int   g_labels[BATCH * HW];
__device__ float g_rn2[BATCH * HW];
__device__ float g_S[BATCH * HW];
__device__ float g_P[BATCH * HW];
__device__ float g_C[BATCH * HW];
__device__ __align__(16) __half g_h[(size_t)BATCH * HW * DIM];

// ================= helpers =================
__device__ __forceinline__ uint32_t smem_u32(const void* p) {
    uint32_t a;
    asm("{ .reg .u64 t; cvta.to.shared.u64 t, %1; cvt.u32.u64 %0, t; }" : "=r"(a) : "l"(p));
    return a;
}
__device__ __forceinline__ void ldsm4(uint32_t* r, uint32_t addr) {
    asm volatile("ldmatrix.sync.aligned.m8n8.x4.shared.b16 {%0,%1,%2,%3}, [%4];"
                 : "=r"(r[0]), "=r"(r[1]), "=r"(r[2]), "=r"(r[3]) : "r"(addr));
}
__device__ __forceinline__ void mma_f16(float* c, const uint32_t* a, const uint32_t* b) {
    asm volatile("mma.sync.aligned.m16n8k16.row.col.f32.f16.f16.f32 "
                 "{%0,%1,%2,%3}, {%4,%5,%6,%7}, {%8,%9}, {%0,%1,%2,%3};"
                 : "+f"(c[0]), "+f"(c[1]), "+f"(c[2]), "+f"(c[3])
                 : "r"(a[0]), "r"(a[1]), "r"(a[2]), "r"(a[3]), "r"(b[0]), "r"(b[1]));
}
__device__ __forceinline__ int PD(int a, int c) { return a * 7 - (a * (a + 1)) / 2 + c; }

// ---------------------------------------------------------------------------
// prep: blocks [0,96) mask-channel active flags; blocks >=96 zero accumulators
// ---------------------------------------------------------------------------
#define ZBLK 224
__global__ void prep_kernel(const float* __restrict__ masks) {
    int blk = blockIdx.x;
    if (blk < BATCH * NMASK) {
        const float* m = masks + (size_t)blk * HW;
        float s = 0.f;
        for (int i = threadIdx.x; i < HW; i += blockDim.x) s += m[i];
        __shared__ float sh[256];
        sh[threadIdx.x] = s;
        __syncthreads();
        for (int o = 128; o > 0; o >>= 1) {
            if (threadIdx.x < o) sh[threadIdx.x] += sh[threadIdx.x + o];
            __syncthreads();
        }
        if (threadIdx.x == 0) g_active[blk] = (sh[0] > 0.f) ? 1 : 0;
    } else {
        int i = (blk - BATCH * NMASK) * 256 + threadIdx.x;
        if (i < BATCH * HW) { g_S[i] = 0.f; g_P[i] = 0.f; g_C[i] = 0.f; }
        if (i < BATCH * NLBL * DIM) ((float*)g_label_sums)[i] = 0.f;
        if (i < BATCH * NLBL) { ((float*)g_cnt)[i] = 0.f; ((float*)g_q)[i] = 0.f; }
    }
}

// ---------------------------------------------------------------------------
// labels
// ---------------------------------------------------------------------------
__global__ void labels_kernel(const float* __restrict__ masks) {
    int idx = blockIdx.x * blockDim.x + threadIdx.x;
    if (idx >= BATCH * HW) return;
    int b = idx / HW, n = idx - b * HW;
    const float* mb = masks + (size_t)b * NMASK * HW;
    int lbl = 0;
#pragma unroll
    for (int m = 0; m < NMASK; m++) {
        if (mb[(size_t)m * HW + n] > 0.5f && g_active[b * NMASK + m]) lbl = m + 1;
    }
    g_labels[idx] = lbl;
}

// ---------------------------------------------------------------------------
// rn2 + fp32 -> fp16 conversion. One warp per pixel.
// ---------------------------------------------------------------------------
__global__ void rn2_cvt_kernel(const float* __restrict__ emb) {
    int w = (blockIdx.x * blockDim.x + threadIdx.x) >> 5;
    int lane = threadIdx.x & 31;
    if (w >= BATCH * HW) return;
    const float4* src = (const float4*)(emb + (size_t)w * DIM) + lane * 4;
    __half hh[16];
    float s = 0.f;
#pragma unroll
    for (int k = 0; k < 4; k++) {
        float4 v = src[k];
        float vv[4] = {v.x, v.y, v.z, v.w};
#pragma unroll
        for (int e = 0; e < 4; e++) {
            float f = vv[e];
            s += f * f;
            hh[k * 4 + e] = __float2half(f);
        }
    }
#pragma unroll
    for (int o = 16; o > 0; o >>= 1) s += __shfl_xor_sync(0xffffffffu, s, o);
    if (lane == 0) g_rn2[w] = s;
    uint4* dh = (uint4*)(g_h + (size_t)w * DIM + lane * 16);
    dh[0] = ((uint4*)hh)[0]; dh[1] = ((uint4*)hh)[1];
}

// ---------------------------------------------------------------------------
// supcon Gram tile via mma.sync fp16 (single product, fp32 accum).
// 128x128 tile per block, 512 threads (16 warps, 32x32 per warp).
// K=512 in 8 chunks of 64, 3-stage cp.async pipeline, one sync per chunk.
// Register epilogue with symmetric row+col scatter.
// ---------------------------------------------------------------------------
__global__ __launch_bounds__(512, 2) void supcon_mma_kernel() {
    extern __shared__ char smem[];
    uint32_t sb = smem_u32(smem);
    int tid = threadIdx.x;
    int wid = tid >> 5, lane = tid & 31;
    int wr = wid >> 2, wc = wid & 3;            // 4x4 warp grid, 32x32 tiles
    int b = blockIdx.y;
    int idx = blockIdx.x, rt = 0;
    while (idx >= CTILES - rt) { idx -= CTILES - rt; rt++; }
    int ct = rt + idx;
    bool diag = (ct == rt);
    int row0 = rt * 128, col0 = ct * 128;

    int* lrow = (int*)(smem + SM_LROW);
    int* lcol = (int*)(smem + SM_LCOL);
    float* rowS = (float*)(smem + SM_ROWS);
    float* rowP = (float*)(smem + SM_ROWP);
    float* rowC = (float*)(smem + SM_ROWC);
    float* colS = (float*)(smem + SM_COLS);
    float* colP = (float*)(smem + SM_COLP);
    float* colC = (float*)(smem + SM_COLC);
    if (tid < 128) {
        int r = row0 + tid, c = col0 + tid;
        lrow[tid] = (r < HW) ? g_labels[b * HW + r] : -1;
        lcol[tid] = (c < HW) ? g_labels[b * HW + c] : -2;
        rowS[tid] = 0.f; rowP[tid] = 0.f; rowC[tid] = 0.f;
        colS[tid] = 0.f; colP[tid] = 0.f; colC[tid] = 0.f;
    }

    const __half* bp = g_h + (size_t)b * HW * DIM;

    // ---- cp.async stage loader: 2 mats x 16KB, 128B rows, xor swizzle ----
    auto load_stage = [&](int c, int buf) {
        uint32_t dst_base = sb + SM_BUF + buf * STAGESZ;
#pragma unroll
        for (int it = 0; it < 4; it++) {
            int mat = it >> 1;                   // 0 = A, 1 = B
            int idxm = tid + 512 * (it & 1);     // 0..1023
            int row = idxm >> 3, seg = idxm & 7;
            int grow = ((mat == 0) ? row0 : col0) + row;
            uint32_t sz = (grow < HW) ? 16u : 0u;
            int gcl = (grow < HW) ? grow : 0;
            const __half* src = bp + (size_t)gcl * DIM + c * 64 + seg * 8;
            uint32_t dst = dst_base + mat * MATSZ + row * 128 +
                           (((uint32_t)(seg * 16)) ^ (((uint32_t)row & 7u) << 4));
            asm volatile("cp.async.cg.shared.global [%0], [%1], 16, %2;"
                         :: "r"(dst), "l"(src), "r"(sz) : "memory");
        }
        asm volatile("cp.async.commit_group;" ::: "memory");
    };

    // fragment address components (128B rows, swizzle mask (row&7)<<4)
    int a_r = wr * 32 + (lane & 15);
    uint32_t a_xm = (((uint32_t)lane) & 7u) << 4;
    uint32_t a_kb = (uint32_t)((lane >> 4) * 16);
    int b_n = wc * 32 + ((lane >> 4) & 1) * 8 + (lane & 7);
    uint32_t b_xm = (((uint32_t)lane) & 7u) << 4;
    uint32_t b_kb = (uint32_t)(((lane >> 3) & 1) * 16);

    float acc[2][4][4];
#pragma unroll
    for (int mt = 0; mt < 2; mt++)
#pragma unroll
        for (int nt = 0; nt < 4; nt++)
#pragma unroll
            for (int e = 0; e < 4; e++) acc[mt][nt][e] = 0.f;

    load_stage(0, 0);
    load_stage(1, 1);
    for (int c = 0; c < 8; c++) {
        if (c < 7) asm volatile("cp.async.wait_group 1;" ::: "memory");
        else       asm volatile("cp.async.wait_group 0;" ::: "memory");
        __syncthreads();   // chunk c visible; all warps done with c-1's buffer
        if (c + 2 < 8) load_stage(c + 2, (c + 2) % NSTAGE);
        uint32_t stg = sb + SM_BUF + (c % NSTAGE) * STAGESZ;
#pragma unroll
        for (int ks = 0; ks < 4; ks++) {
            uint32_t ka = (((uint32_t)(ks * 32)) + a_kb) ^ a_xm;
            uint32_t ah[2][4];
#pragma unroll
            for (int mt = 0; mt < 2; mt++) {
                uint32_t ad = stg + (uint32_t)((a_r + mt * 16) * 128) + ka;
                ldsm4(ah[mt], ad);
            }
            uint32_t kb2 = (((uint32_t)(ks * 32)) + b_kb) ^ b_xm;
#pragma unroll
            for (int ntp = 0; ntp < 2; ntp++) {
                uint32_t bh4[4];
                uint32_t bd = stg + MATSZ + (uint32_t)((b_n + ntp * 16) * 128) + kb2;
                ldsm4(bh4, bd);
#pragma unroll
                for (int mt = 0; mt < 2; mt++) {
                    mma_f16(acc[mt][2 * ntp],     ah[mt], &bh4[0]);
                    mma_f16(acc[mt][2 * ntp + 1], ah[mt], &bh4[2]);
                }
            }
        }
    }
    __syncthreads();

    // ---- register epilogue: rows via shfl(1,2); cols per-nt via shfl(4,8,16) ----
    int lr4 = lane >> 2;
    float S[4], P[4], C4[4];
    int rloc[4], rl[4];
#pragma unroll
    for (int q = 0; q < 4; q++) {
        rloc[q] = wr * 32 + (q >> 1) * 16 + (q & 1) * 8 + lr4;
        rl[q] = lrow[rloc[q]];
        S[q] = P[q] = C4[q] = 0.f;
    }
#pragma unroll
    for (int nt = 0; nt < 4; nt++) {
        int cl0 = wc * 32 + nt * 8 + (lane & 3) * 2;
        int c0l = lcol[cl0], c1l = lcol[cl0 + 1];
        int cg0 = col0 + cl0, cg1 = cg0 + 1;
        float Sc0 = 0.f, Pc0 = 0.f, Cc0 = 0.f;
        float Sc1 = 0.f, Pc1 = 0.f, Cc1 = 0.f;
#pragma unroll
        for (int mt = 0; mt < 2; mt++)
#pragma unroll
            for (int h = 0; h < 2; h++) {
                int q = mt * 2 + h;
                int rg = row0 + rloc[q];
                float d0 = acc[mt][nt][h * 2 + 0], d1 = acc[mt][nt][h * 2 + 1];
                float x0 = (d0 - 1.0f) * INV_T, x1 = (d1 - 1.0f) * INV_T;
                float e0 = __expf(x0), e1 = __expf(x1);
                if (rg < HW && cg0 < HW && cg0 != rg) {
                    S[q] += e0; Sc0 += e0;
                    if (c0l == rl[q]) { P[q] += x0; C4[q] += 1.f; Pc0 += x0; Cc0 += 1.f; }
                }
                if (rg < HW && cg1 < HW && cg1 != rg) {
                    S[q] += e1; Sc1 += e1;
                    if (c1l == rl[q]) { P[q] += x1; C4[q] += 1.f; Pc1 += x1; Cc1 += 1.f; }
                }
            }
        if (!diag) {
#pragma unroll
            for (int o = 4; o <= 16; o <<= 1) {
                Sc0 += __shfl_xor_sync(0xffffffffu, Sc0, o);
                Pc0 += __shfl_xor_sync(0xffffffffu, Pc0, o);
                Cc0 += __shfl_xor_sync(0xffffffffu, Cc0, o);
                Sc1 += __shfl_xor_sync(0xffffffffu, Sc1, o);
                Pc1 += __shfl_xor_sync(0xffffffffu, Pc1, o);
                Cc1 += __shfl_xor_sync(0xffffffffu, Cc1, o);
            }
            if (lane < 4) {
                atomicAdd(&colS[cl0], Sc0);     atomicAdd(&colS[cl0 + 1], Sc1);
                atomicAdd(&colP[cl0], Pc0);     atomicAdd(&colP[cl0 + 1], Pc1);
                atomicAdd(&colC[cl0], Cc0);     atomicAdd(&colC[cl0 + 1], Cc1);
            }
        }
    }
#pragma unroll
    for (int q = 0; q < 4; q++) {
#pragma unroll
        for (int o = 1; o <= 2; o <<= 1) {
            S[q]  += __shfl_xor_sync(0xffffffffu, S[q], o);
            P[q]  += __shfl_xor_sync(0xffffffffu, P[q], o);
            C4[q] += __shfl_xor_sync(0xffffffffu, C4[q], o);
        }
    }
    if ((lane & 3) == 0) {
#pragma unroll
        for (int q = 0; q < 4; q++) {
            atomicAdd(&rowS[rloc[q]], S[q]);
            atomicAdd(&rowP[rloc[q]], P[q]);
            atomicAdd(&rowC[rloc[q]], C4[q]);
        }
    }
    __syncthreads();
    if (tid < 128) {
        int rg = row0 + tid;
        if (rg < HW) {
            atomicAdd(&g_S[b * HW + rg], rowS[tid]);
            atomicAdd(&g_P[b * HW + rg], rowP[tid]);
            atomicAdd(&g_C[b * HW + rg], rowC[tid]);
        }
    } else if (tid < 256 && !diag) {
        int j = tid - 128;
        int cg = col0 + j;
        if (cg < HW) {
            atomicAdd(&g_S[b * HW + cg], colS[j]);
            atomicAdd(&g_P[b * HW + cg], colP[j]);
            atomicAdd(&g_C[b * HW + cg], colC[j]);
        }
    }
}

// ---------------------------------------------------------------------------
// centroids: parallel over (chunk, image), reads the fp16 copy.
// ---------------------------------------------------------------------------
__global__ void centroid_kernel() {
    int chunk = blockIdx.x;
    int b = blockIdx.y;
    int t = threadIdx.x;
    int r0 = chunk * 33, r1 = r0 + 33;
    const __half* fb = g_h + (size_t)b * HW * DIM;
    float acc[NLBL];
#pragma unroll
    for (int l = 0; l < NLBL; l++) acc[l] = 0.f;
#pragma unroll 3
    for (int n = r0; n < r1; n++) {
        int lbl = g_labels[b * HW + n];
        float v = __half2float(fb[(size_t)n * DIM + t]);
#pragma unroll
        for (int l = 0; l < NLBL; l++) acc[l] += (lbl == l) ? v : 0.f;
    }
#pragma unroll
    for (int l = 0; l < NLBL; l++)
        if (acc[l] != 0.f) atomicAdd(&g_label_sums[b][l][t], acc[l]);
    if (t < NLBL) {
        float c = 0.f, q = 0.f;
        for (int n = r0; n < r1; n++) {
            if (g_labels[b * HW + n] == t) { c += 1.f; q += g_rn2[b * HW + n]; }
        }
        if (c != 0.f) { atomicAdd(&g_cnt[b][t], c); atomicAdd(&g_q[b][t], q); }
    }
}

// ---------------------------------------------------------------------------
// merged: blocks [0,16) per-row supcon loss; blocks [16,32) pair-dots.
// ---------------------------------------------------------------------------
__global__ void rowpd_kernel() {
    int t = threadIdx.x;
    if (blockIdx.x < BATCH) {
        int b = blockIdx.x;
        float s = 0.f, n = 0.f;
        for (int r = t; r < HW; r += 512) {
            float c = g_C[b * HW + r];
            if (c > 0.f) {
                s += -((g_P[b * HW + r] - c * logf(g_S[b * HW + r] + 1e-6f)) / c);
                n += 1.f;
            }
        }
        __shared__ float sS[512], sN[512];
        sS[t] = s; sN[t] = n;
        __syncthreads();
        for (int o = 256; o > 0; o >>= 1) {
            if (t < o) { sS[t] += sS[t + o]; sN[t] += sN[t + o]; }
            __syncthreads();
        }
        if (t == 0) { g_supcon_sum[b] = sS[0]; g_anchor_cnt[b] = sN[0]; }
    } else {
        int b = blockIdx.x - BATCH;
        int lane = t & 31;
        float inv[NLBL];
#pragma unroll
        for (int l = 0; l < NLBL; l++) inv[l] = 1.f / fmaxf(g_cnt[b][l], 1.f);
        float raw[NLBL], m[NLBL];
        float sall = 0.f;
#pragma unroll
        for (int l = 0; l < NLBL; l++) {
            raw[l] = g_label_sums[b][l][t];
            m[l] = raw[l] * inv[l];
            sall += raw[l];
        }
        sall *= (1.f / (float)HW);
        float part[NPD];
        int k = 0;
#pragma unroll
        for (int l1 = 0; l1 < NLBL; l1++)
#pragma unroll
            for (int l2 = l1; l2 < NLBL; l2++) part[k++] = m[l1] * m[l2];
        part[28] = sall * sall;
#pragma unroll
        for (int i = 0; i < NPD; i++)
#pragma unroll
            for (int o = 16; o > 0; o >>= 1) part[i] += __shfl_xor_sync(0xffffffffu, part[i], o);
        __shared__ float acc[NPD];
        if (t < NPD) acc[t] = 0.f;
        __syncthreads();
        if (lane == 0) {
#pragma unroll
            for (int i = 0; i < NPD; i++) atomicAdd(&acc[i], part[i]);
        }
        __syncthreads();
        if (t < NPD) g_pd[b][t] = acc[t];
    }
}

// ---------------------------------------------------------------------------
// finalize: pure scalar math from precomputed reductions
// ---------------------------------------------------------------------------
__global__ void finalize_kernel(const float* __restrict__ is_forged, float* __restrict__ out) {
    __shared__ float sc[BATCH], scv[BATCH], sp[BATCH], spv[BATCH], un[BATCH], unv[BATCH];
    int t = threadIdx.x;
    if (t < BATCH) {
        int b = t;
        float na = g_anchor_cnt[b];
        float supcon = g_supcon_sum[b] / fmaxf(na, 1.f);
        float supcon_valid = (na > 0.f) ? 1.f : 0.f;

        float pd[NPD];
#pragma unroll
        for (int i = 0; i < NPD; i++) pd[i] = g_pd[b][i];
        float cnt[NLBL], cn[NLBL], inv[NLBL];
#pragma unroll
        for (int l = 0; l < NLBL; l++) {
            cnt[l] = g_cnt[b][l];
            inv[l] = 1.f / fmaxf(cnt[l], 1.f);
            cn[l] = pd[PD(l, l)];
        }
        float terms = 0.f, npairs = 0.f;
        int npresent = 0;
#pragma unroll
        for (int l = 0; l < NLBL; l++) if (cnt[l] > 0.f) npresent++;
#pragma unroll
        for (int l1 = 0; l1 < NLBL; l1++)
#pragma unroll
            for (int l2 = l1 + 1; l2 < NLBL; l2++) {
                if (cnt[l1] > 0.f && cnt[l2] > 0.f) {
                    float sq = cn[l1] + cn[l2] - 2.f * pd[PD(l1, l2)];
                    float dd = sqrtf(fmaxf(sq, 0.f));
                    terms += fmaxf(SEPM - dd, 0.f);
                    npairs += 1.f;
                }
            }
        float sep = terms / fmaxf(npairs, 1.f);
        float sep_valid = (npresent >= 2) ? 1.f : 0.f;

        float uni, univ;
        if (is_forged[b] >= 0.5f) {
            float inst = 0.f, nl = 0.f;
#pragma unroll
            for (int l = 0; l < NLBL; l++) {
                float var = g_q[b][l] * inv[l] - cn[l];
                if (cnt[l] >= 2.f && var > UNITH) { inst += var - UNITH; nl += 1.f; }
            }
            uni = inst / fmaxf(nl, 1.f);
            univ = (nl > 0.f) ? 1.f : 0.f;
        } else {
            float qall = 0.f;
#pragma unroll
            for (int l = 0; l < NLBL; l++) qall += g_q[b][l];
            float var_all = qall * (1.f / (float)HW) - pd[28];
            uni = (var_all > UNITH) ? (var_all - UNITH) : 0.f;
            univ = (var_all > UNITH) ? 1.f : 0.f;
        }

        sc[b] = supcon * supcon_valid; scv[b] = supcon_valid;
        sp[b] = sep * sep_valid;       spv[b] = sep_valid;
        un[b] = uni * univ;            unv[b] = univ;
    }
    __syncthreads();
    if (t == 0) {
        float a = 0.f, av = 0.f, s2 = 0.f, sv = 0.f, u = 0.f, uv = 0.f;
        for (int b = 0; b < BATCH; b++) {
            a += sc[b]; av += scv[b];
            s2 += sp[b]; sv += spv[b];
            u += un[b]; uv += unv[b];
        }
        float supcon = (av > 0.f) ? a / fmaxf(av, 1.f) : 0.f;
        float sep = (sv > 0.f) ? s2 / fmaxf(sv, 1.f) : 0.f;
        float uni = (uv > 0.f) ? u / fmaxf(uv, 1.f) : 0.f;
        out[0] = 1.0f * supcon + 0.5f * sep + 0.5f * uni;
    }
}

// ---------------------------------------------------------------------------
extern "C" void kernel_launch(void* const* d_in, const int* in_sizes, int n_in,
                              void* d_out, int out_size) {
    const float* emb   = (const float*)d_in[0];   // (16,33,33,512) f32
    const float* masks = (const float*)d_in[1];   // (16,6,33,33) f32
    const float* isf   = (const float*)d_in[2];   // (16,) f32
    float* out = (float*)d_out;

    cudaFuncSetAttribute(supcon_mma_kernel,
                         cudaFuncAttributeMaxDynamicSharedMemorySize, SM_TOTAL);

    prep_kernel<<<BATCH * NMASK + ZBLK, 256>>>(masks);                 // 0
    labels_kernel<<<(BATCH * HW + 255) / 256, 256>>>(masks);           // 1
    rn2_cvt_kernel<<<(BATCH * HW * 32 + 255) / 256, 256>>>(emb);       // 2
    supcon_mma_kernel<<<dim3(NTILEPAIRS, BATCH), 512, SM_TOTAL>>>();   // 3 (ncu slot)
    centroid_kernel<<<dim3(CCH, BATCH), DIM>>>();                      // 4
    rowpd_kernel<<<2 * BATCH, 512>>>();                                // 5
    finalize_kernel<<<1, 32>>>(isf, out);                              // 6
}

// round 12
// speedup vs baseline: 8.0450x; 1.0316x over previous
#include <cuda_runtime.h>
#include <cuda_fp16.h>
#include <cstdint>
#include <math.h>

#define BATCH 16
#define NMASK 6
#define HW 1089
#define DIM 512
#define NLBL 7
#define INV_T (1.0f/0.07f)
#define SEPM 2.0f
#define UNITH 0.1f

#define CTILES 9          // ceil(1089/128)
#define NTILEPAIRS 45     // CTILES*(CTILES+1)/2
#define CCH 33            // centroid chunks (33 rows each)
#define NPD 29            // 28 pair-dots + ||mean_all||^2

// ---- smem layout for supcon_mma (dynamic) ----
#define SM_LROW 0                 // 128 int
#define SM_LCOL 512
#define SM_ROWS 1024
#define SM_ROWP 1536
#define SM_ROWC 2048
#define SM_COLS 2560
#define SM_COLP 3072
#define SM_COLC 3584
#define SM_BUF  4096
#define MATSZ   16384             // 128 rows x 64 fp16 (128B/row)
#define STAGESZ (2*MATSZ)         // A,B = 32KB
#define NSTAGE  3
#define SM_TOTAL (SM_BUF + NSTAGE*STAGESZ)   // 102400 -> 2 CTAs/SM

// ---- scratch (device globals: allocation-free) ----
__device__ float g_label_sums[BATCH][NLBL][DIM];
__device__ float g_cnt[BATCH][NLBL];
__device__ float g_q[BATCH][NLBL];
__device__ float g_supcon_sum[BATCH];
__device__ float g_anchor_cnt[BATCH];
__device__ float g_pd[BATCH][NPD];
__device__ int   g_active[BATCH * NMASK];
__device__ int   g_labels[BATCH * HW];
__device__ float g_rn2[BATCH * HW];
__device__ float g_S[BATCH * HW];
__device__ float g_P[BATCH * HW];
__device__ float g_C[BATCH * HW];
__device__ __align__(16) __half g_h[(size_t)BATCH * HW * DIM];

// ================= helpers =================
__device__ __forceinline__ uint32_t smem_u32(const void* p) {
    uint32_t a;
    asm("{ .reg .u64 t; cvta.to.shared.u64 t, %1; cvt.u32.u64 %0, t; }" : "=r"(a) : "l"(p));
    return a;
}
__device__ __forceinline__ void ldsm4(uint32_t* r, uint32_t addr) {
    asm volatile("ldmatrix.sync.aligned.m8n8.x4.shared.b16 {%0,%1,%2,%3}, [%4];"
                 : "=r"(r[0]), "=r"(r[1]), "=r"(r[2]), "=r"(r[3]) : "r"(addr));
}
__device__ __forceinline__ void mma_f16(float* c, const uint32_t* a, const uint32_t* b) {
    asm volatile("mma.sync.aligned.m16n8k16.row.col.f32.f16.f16.f32 "
                 "{%0,%1,%2,%3}, {%4,%5,%6,%7}, {%8,%9}, {%0,%1,%2,%3};"
                 : "+f"(c[0]), "+f"(c[1]), "+f"(c[2]), "+f"(c[3])
                 : "r"(a[0]), "r"(a[1]), "r"(a[2]), "r"(a[3]), "r"(b[0]), "r"(b[1]));
}
__device__ __forceinline__ int PD(int a, int c) { return a * 7 - (a * (a + 1)) / 2 + c; }

// Fast exp on FMA/ALU pipes (no MUFU): mean-one-tuned Schraudolph.
// exp(x) ~ bits( x * 2^23*log2(e) + (127<<23) - 482524 ), x in [-28.7, 0].
// Per-term mult. error in [-4%, +2%], mean == 1 over uniform fractions, so
// the 1088-term sums S see ~0.1% noise -> ~1e-3 abs on log(S) (acceptable).
__device__ __forceinline__ float fexp(float x) {
    return __int_as_float((int)(fmaf(x, 12102203.0f, 1064870693.0f)));
}

// ---------------------------------------------------------------------------
// fused prep + rn2/cvt:
//   blocks [0,96): mask-channel active flags
//   blocks [96,320): zero accumulators
//   blocks [320,2498): rn2 + fp32->fp16 conversion (one warp per pixel)
// ---------------------------------------------------------------------------
#define ZBLK 224
#define PBLK (BATCH * NMASK + ZBLK)        // 320
#define RBLK ((BATCH * HW) / 8)            // 2178
__global__ void prep_rn2_kernel(const float* __restrict__ masks,
                                const float* __restrict__ emb) {
    int blk = blockIdx.x;
    if (blk < BATCH * NMASK) {
        const float* m = masks + (size_t)blk * HW;
        float s = 0.f;
        for (int i = threadIdx.x; i < HW; i += blockDim.x) s += m[i];
        __shared__ float sh[256];
        sh[threadIdx.x] = s;
        __syncthreads();
        for (int o = 128; o > 0; o >>= 1) {
            if (threadIdx.x < o) sh[threadIdx.x] += sh[threadIdx.x + o];
            __syncthreads();
        }
        if (threadIdx.x == 0) g_active[blk] = (sh[0] > 0.f) ? 1 : 0;
    } else if (blk < PBLK) {
        int i = (blk - BATCH * NMASK) * 256 + threadIdx.x;
        if (i < BATCH * HW) { g_S[i] = 0.f; g_P[i] = 0.f; g_C[i] = 0.f; }
        if (i < BATCH * NLBL * DIM) ((float*)g_label_sums)[i] = 0.f;
        if (i < BATCH * NLBL) { ((float*)g_cnt)[i] = 0.f; ((float*)g_q)[i] = 0.f; }
    } else {
        int w = (blk - PBLK) * 8 + (threadIdx.x >> 5);
        int lane = threadIdx.x & 31;
        const float4* src = (const float4*)(emb + (size_t)w * DIM) + lane * 4;
        __half hh[16];
        float s = 0.f;
#pragma unroll
        for (int k = 0; k < 4; k++) {
            float4 v = src[k];
            float vv[4] = {v.x, v.y, v.z, v.w};
#pragma unroll
            for (int e = 0; e < 4; e++) {
                float f = vv[e];
                s += f * f;
                hh[k * 4 + e] = __float2half(f);
            }
        }
#pragma unroll
        for (int o = 16; o > 0; o >>= 1) s += __shfl_xor_sync(0xffffffffu, s, o);
        if (lane == 0) g_rn2[w] = s;
        uint4* dh = (uint4*)(g_h + (size_t)w * DIM + lane * 16);
        dh[0] = ((uint4*)hh)[0]; dh[1] = ((uint4*)hh)[1];
    }
}

// ---------------------------------------------------------------------------
// labels
// ---------------------------------------------------------------------------
__global__ void labels_kernel(const float* __restrict__ masks) {
    int idx = blockIdx.x * blockDim.x + threadIdx.x;
    if (idx >= BATCH * HW) return;
    int b = idx / HW, n = idx - b * HW;
    const float* mb = masks + (size_t)b * NMASK * HW;
    int lbl = 0;
#pragma unroll
    for (int m = 0; m < NMASK; m++) {
        if (mb[(size_t)m * HW + n] > 0.5f && g_active[b * NMASK + m]) lbl = m + 1;
    }
    g_labels[idx] = lbl;
}

// ---------------------------------------------------------------------------
// supcon Gram tile via mma.sync fp16 (single product, fp32 accum).
// 128x128 tile per block, 512 threads (16 warps, 32x32 per warp).
// K=512 in 8 chunks of 64, 3-stage cp.async pipeline, one sync per chunk.
// Register epilogue with fast-exp (no MUFU) and symmetric row+col scatter.
// ---------------------------------------------------------------------------
__global__ __launch_bounds__(512, 2) void supcon_mma_kernel() {
    extern __shared__ char smem[];
    uint32_t sb = smem_u32(smem);
    int tid = threadIdx.x;
    int wid = tid >> 5, lane = tid & 31;
    int wr = wid >> 2, wc = wid & 3;            // 4x4 warp grid, 32x32 tiles
    int b = blockIdx.y;
    int idx = blockIdx.x, rt = 0;
    while (idx >= CTILES - rt) { idx -= CTILES - rt; rt++; }
    int ct = rt + idx;
    bool diag = (ct == rt);
    int row0 = rt * 128, col0 = ct * 128;

    int* lrow = (int*)(smem + SM_LROW);
    int* lcol = (int*)(smem + SM_LCOL);
    float* rowS = (float*)(smem + SM_ROWS);
    float* rowP = (float*)(smem + SM_ROWP);
    float* rowC = (float*)(smem + SM_ROWC);
    float* colS = (float*)(smem + SM_COLS);
    float* colP = (float*)(smem + SM_COLP);
    float* colC = (float*)(smem + SM_COLC);
    if (tid < 128) {
        int r = row0 + tid, c = col0 + tid;
        lrow[tid] = (r < HW) ? g_labels[b * HW + r] : -1;
        lcol[tid] = (c < HW) ? g_labels[b * HW + c] : -2;
        rowS[tid] = 0.f; rowP[tid] = 0.f; rowC[tid] = 0.f;
        colS[tid] = 0.f; colP[tid] = 0.f; colC[tid] = 0.f;
    }

    const __half* bp = g_h + (size_t)b * HW * DIM;

    // ---- cp.async stage loader: 2 mats x 16KB, 128B rows, xor swizzle ----
    auto load_stage = [&](int c, int buf) {
        uint32_t dst_base = sb + SM_BUF + buf * STAGESZ;
#pragma unroll
        for (int it = 0; it < 4; it++) {
            int mat = it >> 1;                   // 0 = A, 1 = B
            int idxm = tid + 512 * (it & 1);     // 0..1023
            int row = idxm >> 3, seg = idxm & 7;
            int grow = ((mat == 0) ? row0 : col0) + row;
            uint32_t sz = (grow < HW) ? 16u : 0u;
            int gcl = (grow < HW) ? grow : 0;
            const __half* src = bp + (size_t)gcl * DIM + c * 64 + seg * 8;
            uint32_t dst = dst_base + mat * MATSZ + row * 128 +
                           (((uint32_t)(seg * 16)) ^ (((uint32_t)row & 7u) << 4));
            asm volatile("cp.async.cg.shared.global [%0], [%1], 16, %2;"
                         :: "r"(dst), "l"(src), "r"(sz) : "memory");
        }
        asm volatile("cp.async.commit_group;" ::: "memory");
    };

    // fragment address components (128B rows, swizzle mask (row&7)<<4)
    int a_r = wr * 32 + (lane & 15);
    uint32_t a_xm = (((uint32_t)lane) & 7u) << 4;
    uint32_t a_kb = (uint32_t)((lane >> 4) * 16);
    int b_n = wc * 32 + ((lane >> 4) & 1) * 8 + (lane & 7);
    uint32_t b_xm = (((uint32_t)lane) & 7u) << 4;
    uint32_t b_kb = (uint32_t)(((lane >> 3) & 1) * 16);

    float acc[2][4][4];
#pragma unroll
    for (int mt = 0; mt < 2; mt++)
#pragma unroll
        for (int nt = 0; nt < 4; nt++)
#pragma unroll
            for (int e = 0; e < 4; e++) acc[mt][nt][e] = 0.f;

    load_stage(0, 0);
    load_stage(1, 1);
    for (int c = 0; c < 8; c++) {
        if (c < 7) asm volatile("cp.async.wait_group 1;" ::: "memory");
        else       asm volatile("cp.async.wait_group 0;" ::: "memory");
        __syncthreads();   // chunk c visible; all warps done with c-1's buffer
        if (c + 2 < 8) load_stage(c + 2, (c + 2) % NSTAGE);
        uint32_t stg = sb + SM_BUF + (c % NSTAGE) * STAGESZ;
#pragma unroll
        for (int ks = 0; ks < 4; ks++) {
            uint32_t ka = (((uint32_t)(ks * 32)) + a_kb) ^ a_xm;
            uint32_t ah[2][4];
#pragma unroll
            for (int mt = 0; mt < 2; mt++) {
                uint32_t ad = stg + (uint32_t)((a_r + mt * 16) * 128) + ka;
                ldsm4(ah[mt], ad);
            }
            uint32_t kb2 = (((uint32_t)(ks * 32)) + b_kb) ^ b_xm;
#pragma unroll
            for (int ntp = 0; ntp < 2; ntp++) {
                uint32_t bh4[4];
                uint32_t bd = stg + MATSZ + (uint32_t)((b_n + ntp * 16) * 128) + kb2;
                ldsm4(bh4, bd);
#pragma unroll
                for (int mt = 0; mt < 2; mt++) {
                    mma_f16(acc[mt][2 * ntp],     ah[mt], &bh4[0]);
                    mma_f16(acc[mt][2 * ntp + 1], ah[mt], &bh4[2]);
                }
            }
        }
    }
    __syncthreads();

    // ---- register epilogue: rows via shfl(1,2); cols per-nt via shfl(4,8,16) ----
    int lr4 = lane >> 2;
    float S[4], P[4], C4[4];
    int rloc[4], rl[4];
#pragma unroll
    for (int q = 0; q < 4; q++) {
        rloc[q] = wr * 32 + (q >> 1) * 16 + (q & 1) * 8 + lr4;
        rl[q] = lrow[rloc[q]];
        S[q] = P[q] = C4[q] = 0.f;
    }
#pragma unroll
    for (int nt = 0; nt < 4; nt++) {
        int cl0 = wc * 32 + nt * 8 + (lane & 3) * 2;
        int c0l = lcol[cl0], c1l = lcol[cl0 + 1];
        int cg0 = col0 + cl0, cg1 = cg0 + 1;
        float Sc0 = 0.f, Pc0 = 0.f, Cc0 = 0.f;
        float Sc1 = 0.f, Pc1 = 0.f, Cc1 = 0.f;
#pragma unroll
        for (int mt = 0; mt < 2; mt++)
#pragma unroll
            for (int h = 0; h < 2; h++) {
                int q = mt * 2 + h;
                int rg = row0 + rloc[q];
                float d0 = acc[mt][nt][h * 2 + 0], d1 = acc[mt][nt][h * 2 + 1];
                float x0 = (d0 - 1.0f) * INV_T, x1 = (d1 - 1.0f) * INV_T;
                float e0 = fexp(x0), e1 = fexp(x1);
                if (rg < HW && cg0 < HW && cg0 != rg) {
                    S[q] += e0; Sc0 += e0;
                    if (c0l == rl[q]) { P[q] += x0; C4[q] += 1.f; Pc0 += x0; Cc0 += 1.f; }
                }
                if (rg < HW && cg1 < HW && cg1 != rg) {
                    S[q] += e1; Sc1 += e1;
                    if (c1l == rl[q]) { P[q] += x1; C4[q] += 1.f; Pc1 += x1; Cc1 += 1.f; }
                }
            }
        if (!diag) {
#pragma unroll
            for (int o = 4; o <= 16; o <<= 1) {
                Sc0 += __shfl_xor_sync(0xffffffffu, Sc0, o);
                Pc0 += __shfl_xor_sync(0xffffffffu, Pc0, o);
                Cc0 += __shfl_xor_sync(0xffffffffu, Cc0, o);
                Sc1 += __shfl_xor_sync(0xffffffffu, Sc1, o);
                Pc1 += __shfl_xor_sync(0xffffffffu, Pc1, o);
                Cc1 += __shfl_xor_sync(0xffffffffu, Cc1, o);
            }
            if (lane < 4) {
                atomicAdd(&colS[cl0], Sc0);     atomicAdd(&colS[cl0 + 1], Sc1);
                atomicAdd(&colP[cl0], Pc0);     atomicAdd(&colP[cl0 + 1], Pc1);
                atomicAdd(&colC[cl0], Cc0);     atomicAdd(&colC[cl0 + 1], Cc1);
            }
        }
    }
#pragma unroll
    for (int q = 0; q < 4; q++) {
#pragma unroll
        for (int o = 1; o <= 2; o <<= 1) {
            S[q]  += __shfl_xor_sync(0xffffffffu, S[q], o);
            P[q]  += __shfl_xor_sync(0xffffffffu, P[q], o);
            C4[q] += __shfl_xor_sync(0xffffffffu, C4[q], o);
        }
    }
    if ((lane & 3) == 0) {
#pragma unroll
        for (int q = 0; q < 4; q++) {
            atomicAdd(&rowS[rloc[q]], S[q]);
            atomicAdd(&rowP[rloc[q]], P[q]);
            atomicAdd(&rowC[rloc[q]], C4[q]);
        }
    }
    __syncthreads();
    if (tid < 128) {
        int rg = row0 + tid;
        if (rg < HW) {
            atomicAdd(&g_S[b * HW + rg], rowS[tid]);
            atomicAdd(&g_P[b * HW + rg], rowP[tid]);
            atomicAdd(&g_C[b * HW + rg], rowC[tid]);
        }
    } else if (tid < 256 && !diag) {
        int j = tid - 128;
        int cg = col0 + j;
        if (cg < HW) {
            atomicAdd(&g_S[b * HW + cg], colS[j]);
            atomicAdd(&g_P[b * HW + cg], colP[j]);
            atomicAdd(&g_C[b * HW + cg], colC[j]);
        }
    }
}

// ---------------------------------------------------------------------------
// centroids: parallel over (chunk, image), reads the fp16 copy.
// ---------------------------------------------------------------------------
__global__ void centroid_kernel() {
    int chunk = blockIdx.x;
    int b = blockIdx.y;
    int t = threadIdx.x;
    int r0 = chunk * 33, r1 = r0 + 33;
    const __half* fb = g_h + (size_t)b * HW * DIM;
    float acc[NLBL];
#pragma unroll
    for (int l = 0; l < NLBL; l++) acc[l] = 0.f;
#pragma unroll 3
    for (int n = r0; n < r1; n++) {
        int lbl = g_labels[b * HW + n];
        float v = __half2float(fb[(size_t)n * DIM + t]);
#pragma unroll
        for (int l = 0; l < NLBL; l++) acc[l] += (lbl == l) ? v : 0.f;
    }
#pragma unroll
    for (int l = 0; l < NLBL; l++)
        if (acc[l] != 0.f) atomicAdd(&g_label_sums[b][l][t], acc[l]);
    if (t < NLBL) {
        float c = 0.f, q = 0.f;
        for (int n = r0; n < r1; n++) {
            if (g_labels[b * HW + n] == t) { c += 1.f; q += g_rn2[b * HW + n]; }
        }
        if (c != 0.f) { atomicAdd(&g_cnt[b][t], c); atomicAdd(&g_q[b][t], q); }
    }
}

// ---------------------------------------------------------------------------
// merged: blocks [0,16) per-row supcon loss; blocks [16,32) pair-dots.
// ---------------------------------------------------------------------------
__global__ void rowpd_kernel() {
    int t = threadIdx.x;
    if (blockIdx.x < BATCH) {
        int b = blockIdx.x;
        float s = 0.f, n = 0.f;
        for (int r = t; r < HW; r += 512) {
            float c = g_C[b * HW + r];
            if (c > 0.f) {
                s += -((g_P[b * HW + r] - c * logf(g_S[b * HW + r] + 1e-6f)) / c);
                n += 1.f;
            }
        }
        __shared__ float sS[512], sN[512];
        sS[t] = s; sN[t] = n;
        __syncthreads();
        for (int o = 256; o > 0; o >>= 1) {
            if (t < o) { sS[t] += sS[t + o]; sN[t] += sN[t + o]; }
            __syncthreads();
        }
        if (t == 0) { g_supcon_sum[b] = sS[0]; g_anchor_cnt[b] = sN[0]; }
    } else {
        int b = blockIdx.x - BATCH;
        int lane = t & 31;
        float inv[NLBL];
#pragma unroll
        for (int l = 0; l < NLBL; l++) inv[l] = 1.f / fmaxf(g_cnt[b][l], 1.f);
        float raw[NLBL], m[NLBL];
        float sall = 0.f;
#pragma unroll
        for (int l = 0; l < NLBL; l++) {
            raw[l] = g_label_sums[b][l][t];
            m[l] = raw[l] * inv[l];
            sall += raw[l];
        }
        sall *= (1.f / (float)HW);
        float part[NPD];
        int k = 0;
#pragma unroll
        for (int l1 = 0; l1 < NLBL; l1++)
#pragma unroll
            for (int l2 = l1; l2 < NLBL; l2++) part[k++] = m[l1] * m[l2];
        part[28] = sall * sall;
#pragma unroll
        for (int i = 0; i < NPD; i++)
#pragma unroll
            for (int o = 16; o > 0; o >>= 1) part[i] += __shfl_xor_sync(0xffffffffu, part[i], o);
        __shared__ float acc[NPD];
        if (t < NPD) acc[t] = 0.f;
        __syncthreads();
        if (lane == 0) {
#pragma unroll
            for (int i = 0; i < NPD; i++) atomicAdd(&acc[i], part[i]);
        }
        __syncthreads();
        if (t < NPD) g_pd[b][t] = acc[t];
    }
}

// ---------------------------------------------------------------------------
// finalize: pure scalar math from precomputed reductions
// ---------------------------------------------------------------------------
__global__ void finalize_kernel(const float* __restrict__ is_forged, float* __restrict__ out) {
    __shared__ float sc[BATCH], scv[BATCH], sp[BATCH], spv[BATCH], un[BATCH], unv[BATCH];
    int t = threadIdx.x;
    if (t < BATCH) {
        int b = t;
        float na = g_anchor_cnt[b];
        float supcon = g_supcon_sum[b] / fmaxf(na, 1.f);
        float supcon_valid = (na > 0.f) ? 1.f : 0.f;

        float pd[NPD];
#pragma unroll
        for (int i = 0; i < NPD; i++) pd[i] = g_pd[b][i];
        float cnt[NLBL], cn[NLBL], inv[NLBL];
#pragma unroll
        for (int l = 0; l < NLBL; l++) {
            cnt[l] = g_cnt[b][l];
            inv[l] = 1.f / fmaxf(cnt[l], 1.f);
            cn[l] = pd[PD(l, l)];
        }
        float terms = 0.f, npairs = 0.f;
        int npresent = 0;
#pragma unroll
        for (int l = 0; l < NLBL; l++) if (cnt[l] > 0.f) npresent++;
#pragma unroll
        for (int l1 = 0; l1 < NLBL; l1++)
#pragma unroll
            for (int l2 = l1 + 1; l2 < NLBL; l2++) {
                if (cnt[l1] > 0.f && cnt[l2] > 0.f) {
                    float sq = cn[l1] + cn[l2] - 2.f * pd[PD(l1, l2)];
                    float dd = sqrtf(fmaxf(sq, 0.f));
                    terms += fmaxf(SEPM - dd, 0.f);
                    npairs += 1.f;
                }
            }
        float sep = terms / fmaxf(npairs, 1.f);
        float sep_valid = (npresent >= 2) ? 1.f : 0.f;

        float uni, univ;
        if (is_forged[b] >= 0.5f) {
            float inst = 0.f, nl = 0.f;
#pragma unroll
            for (int l = 0; l < NLBL; l++) {
                float var = g_q[b][l] * inv[l] - cn[l];
                if (cnt[l] >= 2.f && var > UNITH) { inst += var - UNITH; nl += 1.f; }
            }
            uni = inst / fmaxf(nl, 1.f);
            univ = (nl > 0.f) ? 1.f : 0.f;
        } else {
            float qall = 0.f;
#pragma unroll
            for (int l = 0; l < NLBL; l++) qall += g_q[b][l];
            float var_all = qall * (1.f / (float)HW) - pd[28];
            uni = (var_all > UNITH) ? (var_all - UNITH) : 0.f;
            univ = (var_all > UNITH) ? 1.f : 0.f;
        }

        sc[b] = supcon * supcon_valid; scv[b] = supcon_valid;
        sp[b] = sep * sep_valid;       spv[b] = sep_valid;
        un[b] = uni * univ;            unv[b] = univ;
    }
    __syncthreads();
    if (t == 0) {
        float a = 0.f, av = 0.f, s2 = 0.f, sv = 0.f, u = 0.f, uv = 0.f;
        for (int b = 0; b < BATCH; b++) {
            a += sc[b]; av += scv[b];
            s2 += sp[b]; sv += spv[b];
            u += un[b]; uv += unv[b];
        }
        float supcon = (av > 0.f) ? a / fmaxf(av, 1.f) : 0.f;
        float sep = (sv > 0.f) ? s2 / fmaxf(sv, 1.f) : 0.f;
        float uni = (uv > 0.f) ? u / fmaxf(uv, 1.f) : 0.f;
        out[0] = 1.0f * supcon + 0.5f * sep + 0.5f * uni;
    }
}

// ---------------------------------------------------------------------------
extern "C" void kernel_launch(void* const* d_in, const int* in_sizes, int n_in,
                              void* d_out, int out_size) {
    const float* emb   = (const float*)d_in[0];   // (16,33,33,512) f32
    const float* masks = (const float*)d_in[1];   // (16,6,33,33) f32
    const float* isf   = (const float*)d_in[2];   // (16,) f32
    float* out = (float*)d_out;

    cudaFuncSetAttribute(supcon_mma_kernel,
                         cudaFuncAttributeMaxDynamicSharedMemorySize, SM_TOTAL);

    prep_rn2_kernel<<<PBLK + RBLK, 256>>>(masks, emb);                 // 0
    labels_kernel<<<(BATCH * HW + 255) / 256, 256>>>(masks);           // 1
    supcon_mma_kernel<<<dim3(NTILEPAIRS, BATCH), 512, SM_TOTAL>>>();   // 2
    centroid_kernel<<<dim3(CCH, BATCH), DIM>>>();                      // 3
    rowpd_kernel<<<2 * BATCH, 512>>>();                                // 4
    finalize_kernel<<<1, 32>>>(isf, out);                              // 5
}

// round 13
// speedup vs baseline: 8.3894x; 1.0428x over previous
#include <cuda_runtime.h>
#include <cuda_fp16.h>
#include <cstdint>
#include <math.h>

#define BATCH 16
#define NMASK 6
#define HW 1089
#define DIM 512
#define NLBL 7
#define INV_T (1.0f/0.07f)
#define SEPM 2.0f
#define UNITH 0.1f

#define CTILES 9          // ceil(1089/128)
#define NTILEPAIRS 45     // CTILES*(CTILES+1)/2
#define NPD 29            // 28 pair-dots + ||mean_all||^2

// ---- smem layout for supcon_mma (dynamic) ----
#define SM_LROW 0                 // 128 int
#define SM_LCOL 512
#define SM_ROWS 1024
#define SM_ROWP 1536
#define SM_ROWC 2048
#define SM_COLS 2560
#define SM_COLP 3072
#define SM_COLC 3584
#define SM_BUF  4096
#define MATSZ   16384             // 128 rows x 64 fp16 (128B/row)
#define STAGESZ (2*MATSZ)         // A,B = 32KB
#define NSTAGE  3
#define SM_TOTAL (SM_BUF + NSTAGE*STAGESZ)   // 102400 -> 2 CTAs/SM

// ---- scratch (device globals: allocation-free) ----
__device__ float g_label_sums[BATCH][NLBL][DIM];
__device__ float g_cnt[BATCH][NLBL];
__device__ float g_supcon_sum[BATCH];
__device__ float g_anchor_cnt[BATCH];
__device__ float g_pd[BATCH][NPD];
__device__ int   g_active[BATCH * NMASK];
__device__ int   g_labels[BATCH * HW];
__device__ float g_S[BATCH * HW];
__device__ float g_P[BATCH * HW];
__device__ float g_C[BATCH * HW];
__device__ __align__(16) __half g_h[(size_t)BATCH * HW * DIM];

// ================= helpers =================
__device__ __forceinline__ uint32_t smem_u32(const void* p) {
    uint32_t a;
    asm("{ .reg .u64 t; cvta.to.shared.u64 t, %1; cvt.u32.u64 %0, t; }" : "=r"(a) : "l"(p));
    return a;
}
__device__ __forceinline__ void ldsm4(uint32_t* r, uint32_t addr) {
    asm volatile("ldmatrix.sync.aligned.m8n8.x4.shared.b16 {%0,%1,%2,%3}, [%4];"
                 : "=r"(r[0]), "=r"(r[1]), "=r"(r[2]), "=r"(r[3]) : "r"(addr));
}
__device__ __forceinline__ void mma_f16(float* c, const uint32_t* a, const uint32_t* b) {
    asm volatile("mma.sync.aligned.m16n8k16.row.col.f32.f16.f16.f32 "
                 "{%0,%1,%2,%3}, {%4,%5,%6,%7}, {%8,%9}, {%0,%1,%2,%3};"
                 : "+f"(c[0]), "+f"(c[1]), "+f"(c[2]), "+f"(c[3])
                 : "r"(a[0]), "r"(a[1]), "r"(a[2]), "r"(a[3]), "r"(b[0]), "r"(b[1]));
}
__device__ __forceinline__ int PD(int a, int c) { return a * 7 - (a * (a + 1)) / 2 + c; }

// Fast exp on FMA/ALU pipes (no MUFU): mean-one-tuned Schraudolph.
__device__ __forceinline__ float fexp(float x) {
    return __int_as_float((int)(fmaf(x, 12102203.0f, 1064870693.0f)));
}

// ---------------------------------------------------------------------------
// prep: blocks [0,96) mask-channel active flags; blocks >=96 zero accumulators
// ---------------------------------------------------------------------------
#define ZBLK 224
#define PBLK (BATCH * NMASK + ZBLK)        // 320
__global__ void prep_kernel(const float* __restrict__ masks) {
    int blk = blockIdx.x;
    if (blk < BATCH * NMASK) {
        const float* m = masks + (size_t)blk * HW;
        float s = 0.f;
        for (int i = threadIdx.x; i < HW; i += blockDim.x) s += m[i];
        __shared__ float sh[256];
        sh[threadIdx.x] = s;
        __syncthreads();
        for (int o = 128; o > 0; o >>= 1) {
            if (threadIdx.x < o) sh[threadIdx.x] += sh[threadIdx.x + o];
            __syncthreads();
        }
        if (threadIdx.x == 0) g_active[blk] = (sh[0] > 0.f) ? 1 : 0;
    } else {
        int i = (blk - BATCH * NMASK) * 256 + threadIdx.x;
        if (i < BATCH * HW) { g_S[i] = 0.f; g_P[i] = 0.f; g_C[i] = 0.f; }
        if (i < BATCH * NLBL * DIM) ((float*)g_label_sums)[i] = 0.f;
        if (i < BATCH * NLBL) ((float*)g_cnt)[i] = 0.f;
    }
}

// ---------------------------------------------------------------------------
// cvt: pure streaming fp32 -> fp16 (8 elements per thread). rn2 == 1 exactly
// (reference normalizes embeddings), so no norm computation needed.
// ---------------------------------------------------------------------------
#define CVTBLK ((BATCH * HW * DIM) / (256 * 8))   // 4356
__global__ void cvt_kernel(const float* __restrict__ emb) {
    size_t i = ((size_t)blockIdx.x * 256 + threadIdx.x) * 8;
    float4 v0 = *(const float4*)(emb + i);
    float4 v1 = *(const float4*)(emb + i + 4);
    __half hh[8];
    hh[0] = __float2half(v0.x); hh[1] = __float2half(v0.y);
    hh[2] = __float2half(v0.z); hh[3] = __float2half(v0.w);
    hh[4] = __float2half(v1.x); hh[5] = __float2half(v1.y);
    hh[6] = __float2half(v1.z); hh[7] = __float2half(v1.w);
    *(uint4*)(g_h + i) = *(uint4*)hh;
}

// ---------------------------------------------------------------------------
// labels
// ---------------------------------------------------------------------------
__global__ void labels_kernel(const float* __restrict__ masks) {
    int idx = blockIdx.x * blockDim.x + threadIdx.x;
    if (idx >= BATCH * HW) return;
    int b = idx / HW, n = idx - b * HW;
    const float* mb = masks + (size_t)b * NMASK * HW;
    int lbl = 0;
#pragma unroll
    for (int m = 0; m < NMASK; m++) {
        if (mb[(size_t)m * HW + n] > 0.5f && g_active[b * NMASK + m]) lbl = m + 1;
    }
    g_labels[idx] = lbl;
}

// ---------------------------------------------------------------------------
// supcon Gram tile via mma.sync fp16 (single product, fp32 accum).
// 128x128 tile per block, 512 threads (16 warps, 32x32 per warp).
// K=512 in 8 chunks of 64, 3-stage cp.async pipeline, one sync per chunk.
// Register epilogue with fast-exp (no MUFU) and symmetric row+col scatter.
// ---------------------------------------------------------------------------
__global__ __launch_bounds__(512, 2) void supcon_mma_kernel() {
    extern __shared__ char smem[];
    uint32_t sb = smem_u32(smem);
    int tid = threadIdx.x;
    int wid = tid >> 5, lane = tid & 31;
    int wr = wid >> 2, wc = wid & 3;            // 4x4 warp grid, 32x32 tiles
    int b = blockIdx.y;
    int idx = blockIdx.x, rt = 0;
    while (idx >= CTILES - rt) { idx -= CTILES - rt; rt++; }
    int ct = rt + idx;
    bool diag = (ct == rt);
    int row0 = rt * 128, col0 = ct * 128;

    int* lrow = (int*)(smem + SM_LROW);
    int* lcol = (int*)(smem + SM_LCOL);
    float* rowS = (float*)(smem + SM_ROWS);
    float* rowP = (float*)(smem + SM_ROWP);
    float* rowC = (float*)(smem + SM_ROWC);
    float* colS = (float*)(smem + SM_COLS);
    float* colP = (float*)(smem + SM_COLP);
    float* colC = (float*)(smem + SM_COLC);
    if (tid < 128) {
        int r = row0 + tid, c = col0 + tid;
        lrow[tid] = (r < HW) ? g_labels[b * HW + r] : -1;
        lcol[tid] = (c < HW) ? g_labels[b * HW + c] : -2;
        rowS[tid] = 0.f; rowP[tid] = 0.f; rowC[tid] = 0.f;
        colS[tid] = 0.f; colP[tid] = 0.f; colC[tid] = 0.f;
    }

    const __half* bp = g_h + (size_t)b * HW * DIM;

    // ---- cp.async stage loader: 2 mats x 16KB, 128B rows, xor swizzle ----
    auto load_stage = [&](int c, int buf) {
        uint32_t dst_base = sb + SM_BUF + buf * STAGESZ;
#pragma unroll
        for (int it = 0; it < 4; it++) {
            int mat = it >> 1;                   // 0 = A, 1 = B
            int idxm = tid + 512 * (it & 1);     // 0..1023
            int row = idxm >> 3, seg = idxm & 7;
            int grow = ((mat == 0) ? row0 : col0) + row;
            uint32_t sz = (grow < HW) ? 16u : 0u;
            int gcl = (grow < HW) ? grow : 0;
            const __half* src = bp + (size_t)gcl * DIM + c * 64 + seg * 8;
            uint32_t dst = dst_base + mat * MATSZ + row * 128 +
                           (((uint32_t)(seg * 16)) ^ (((uint32_t)row & 7u) << 4));
            asm volatile("cp.async.cg.shared.global [%0], [%1], 16, %2;"
                         :: "r"(dst), "l"(src), "r"(sz) : "memory");
        }
        asm volatile("cp.async.commit_group;" ::: "memory");
    };

    // fragment address components (128B rows, swizzle mask (row&7)<<4)
    int a_r = wr * 32 + (lane & 15);
    uint32_t a_xm = (((uint32_t)lane) & 7u) << 4;
    uint32_t a_kb = (uint32_t)((lane >> 4) * 16);
    int b_n = wc * 32 + ((lane >> 4) & 1) * 8 + (lane & 7);
    uint32_t b_xm = (((uint32_t)lane) & 7u) << 4;
    uint32_t b_kb = (uint32_t)(((lane >> 3) & 1) * 16);

    float acc[2][4][4];
#pragma unroll
    for (int mt = 0; mt < 2; mt++)
#pragma unroll
        for (int nt = 0; nt < 4; nt++)
#pragma unroll
            for (int e = 0; e < 4; e++) acc[mt][nt][e] = 0.f;

    load_stage(0, 0);
    load_stage(1, 1);
    for (int c = 0; c < 8; c++) {
        if (c < 7) asm volatile("cp.async.wait_group 1;" ::: "memory");
        else       asm volatile("cp.async.wait_group 0;" ::: "memory");
        __syncthreads();   // chunk c visible; all warps done with c-1's buffer
        if (c + 2 < 8) load_stage(c + 2, (c + 2) % NSTAGE);
        uint32_t stg = sb + SM_BUF + (c % NSTAGE) * STAGESZ;
#pragma unroll
        for (int ks = 0; ks < 4; ks++) {
            uint32_t ka = (((uint32_t)(ks * 32)) + a_kb) ^ a_xm;
            uint32_t ah[2][4];
#pragma unroll
            for (int mt = 0; mt < 2; mt++) {
                uint32_t ad = stg + (uint32_t)((a_r + mt * 16) * 128) + ka;
                ldsm4(ah[mt], ad);
            }
            uint32_t kb2 = (((uint32_t)(ks * 32)) + b_kb) ^ b_xm;
#pragma unroll
            for (int ntp = 0; ntp < 2; ntp++) {
                uint32_t bh4[4];
                uint32_t bd = stg + MATSZ + (uint32_t)((b_n + ntp * 16) * 128) + kb2;
                ldsm4(bh4, bd);
#pragma unroll
                for (int mt = 0; mt < 2; mt++) {
                    mma_f16(acc[mt][2 * ntp],     ah[mt], &bh4[0]);
                    mma_f16(acc[mt][2 * ntp + 1], ah[mt], &bh4[2]);
                }
            }
        }
    }
    __syncthreads();

    // ---- register epilogue: rows via shfl(1,2); cols per-nt via shfl(4,8,16) ----
    int lr4 = lane >> 2;
    float S[4], P[4], C4[4];
    int rloc[4], rl[4];
#pragma unroll
    for (int q = 0; q < 4; q++) {
        rloc[q] = wr * 32 + (q >> 1) * 16 + (q & 1) * 8 + lr4;
        rl[q] = lrow[rloc[q]];
        S[q] = P[q] = C4[q] = 0.f;
    }
#pragma unroll
    for (int nt = 0; nt < 4; nt++) {
        int cl0 = wc * 32 + nt * 8 + (lane & 3) * 2;
        int c0l = lcol[cl0], c1l = lcol[cl0 + 1];
        int cg0 = col0 + cl0, cg1 = cg0 + 1;
        float Sc0 = 0.f, Pc0 = 0.f, Cc0 = 0.f;
        float Sc1 = 0.f, Pc1 = 0.f, Cc1 = 0.f;
#pragma unroll
        for (int mt = 0; mt < 2; mt++)
#pragma unroll
            for (int h = 0; h < 2; h++) {
                int q = mt * 2 + h;
                int rg = row0 + rloc[q];
                float d0 = acc[mt][nt][h * 2 + 0], d1 = acc[mt][nt][h * 2 + 1];
                float x0 = (d0 - 1.0f) * INV_T, x1 = (d1 - 1.0f) * INV_T;
                float e0 = fexp(x0), e1 = fexp(x1);
                if (rg < HW && cg0 < HW && cg0 != rg) {
                    S[q] += e0; Sc0 += e0;
                    if (c0l == rl[q]) { P[q] += x0; C4[q] += 1.f; Pc0 += x0; Cc0 += 1.f; }
                }
                if (rg < HW && cg1 < HW && cg1 != rg) {
                    S[q] += e1; Sc1 += e1;
                    if (c1l == rl[q]) { P[q] += x1; C4[q] += 1.f; Pc1 += x1; Cc1 += 1.f; }
                }
            }
        if (!diag) {
#pragma unroll
            for (int o = 4; o <= 16; o <<= 1) {
                Sc0 += __shfl_xor_sync(0xffffffffu, Sc0, o);
                Pc0 += __shfl_xor_sync(0xffffffffu, Pc0, o);
                Cc0 += __shfl_xor_sync(0xffffffffu, Cc0, o);
                Sc1 += __shfl_xor_sync(0xffffffffu, Sc1, o);
                Pc1 += __shfl_xor_sync(0xffffffffu, Pc1, o);
                Cc1 += __shfl_xor_sync(0xffffffffu, Cc1, o);
            }
            if (lane < 4) {
                atomicAdd(&colS[cl0], Sc0);     atomicAdd(&colS[cl0 + 1], Sc1);
                atomicAdd(&colP[cl0], Pc0);     atomicAdd(&colP[cl0 + 1], Pc1);
                atomicAdd(&colC[cl0], Cc0);     atomicAdd(&colC[cl0 + 1], Cc1);
            }
        }
    }
#pragma unroll
    for (int q = 0; q < 4; q++) {
#pragma unroll
        for (int o = 1; o <= 2; o <<= 1) {
            S[q]  += __shfl_xor_sync(0xffffffffu, S[q], o);
            P[q]  += __shfl_xor_sync(0xffffffffu, P[q], o);
            C4[q] += __shfl_xor_sync(0xffffffffu, C4[q], o);
        }
    }
    if ((lane & 3) == 0) {
#pragma unroll
        for (int q = 0; q < 4; q++) {
            atomicAdd(&rowS[rloc[q]], S[q]);
            atomicAdd(&rowP[rloc[q]], P[q]);
            atomicAdd(&rowC[rloc[q]], C4[q]);
        }
    }
    __syncthreads();
    if (tid < 128) {
        int rg = row0 + tid;
        if (rg < HW) {
            atomicAdd(&g_S[b * HW + rg], rowS[tid]);
            atomicAdd(&g_P[b * HW + rg], rowP[tid]);
            atomicAdd(&g_C[b * HW + rg], rowC[tid]);
        }
    } else if (tid < 256 && !diag) {
        int j = tid - 128;
        int cg = col0 + j;
        if (cg < HW) {
            atomicAdd(&g_S[b * HW + cg], colS[j]);
            atomicAdd(&g_P[b * HW + cg], colP[j]);
            atomicAdd(&g_C[b * HW + cg], colC[j]);
        }
    }
}

// ---------------------------------------------------------------------------
// centroids: compact-then-accumulate. Block = (chunk, label, image).
// Gathers matching row indices to smem, then unroll-4 accumulation:
// one FADD per element (vs 7 predicated) and MLP ~4 on the loads.
// ---------------------------------------------------------------------------
#define CCHUNK 2
#define CROWS 545          // ceil(1089/2)
__global__ void centroid_kernel() {
    __shared__ int slist[CROWS];
    __shared__ int scnt;
    int ch = blockIdx.x, l = blockIdx.y, b = blockIdx.z;
    int t = threadIdx.x;
    int r0 = ch * CROWS;
    int r1 = (r0 + CROWS < HW) ? r0 + CROWS : HW;
    if (t == 0) scnt = 0;
    __syncthreads();
    for (int n = r0 + t; n < r1; n += 512) {
        if (g_labels[b * HW + n] == l) slist[atomicAdd(&scnt, 1)] = n;
    }
    __syncthreads();
    int cnt = scnt;
    if (cnt == 0) return;
    const __half* fb = g_h + (size_t)b * HW * DIM;
    float acc = 0.f;
    int i = 0;
    for (; i + 4 <= cnt; i += 4) {
        float v0 = __half2float(fb[(size_t)slist[i + 0] * DIM + t]);
        float v1 = __half2float(fb[(size_t)slist[i + 1] * DIM + t]);
        float v2 = __half2float(fb[(size_t)slist[i + 2] * DIM + t]);
        float v3 = __half2float(fb[(size_t)slist[i + 3] * DIM + t]);
        acc += (v0 + v1) + (v2 + v3);
    }
    for (; i < cnt; i++)
        acc += __half2float(fb[(size_t)slist[i] * DIM + t]);
    atomicAdd(&g_label_sums[b][l][t], acc);
    if (t == 0) atomicAdd(&g_cnt[b][l], (float)cnt);
}

// ---------------------------------------------------------------------------
// merged: blocks [0,16) per-row supcon loss; blocks [16,32) pair-dots.
// ---------------------------------------------------------------------------
__global__ void rowpd_kernel() {
    int t = threadIdx.x;
    if (blockIdx.x < BATCH) {
        int b = blockIdx.x;
        float s = 0.f, n = 0.f;
        for (int r = t; r < HW; r += 512) {
            float c = g_C[b * HW + r];
            if (c > 0.f) {
                s += -((g_P[b * HW + r] - c * logf(g_S[b * HW + r] + 1e-6f)) / c);
                n += 1.f;
            }
        }
        __shared__ float sS[512], sN[512];
        sS[t] = s; sN[t] = n;
        __syncthreads();
        for (int o = 256; o > 0; o >>= 1) {
            if (t < o) { sS[t] += sS[t + o]; sN[t] += sN[t + o]; }
            __syncthreads();
        }
        if (t == 0) { g_supcon_sum[b] = sS[0]; g_anchor_cnt[b] = sN[0]; }
    } else {
        int b = blockIdx.x - BATCH;
        int lane = t & 31;
        float inv[NLBL];
#pragma unroll
        for (int l = 0; l < NLBL; l++) inv[l] = 1.f / fmaxf(g_cnt[b][l], 1.f);
        float raw[NLBL], m[NLBL];
        float sall = 0.f;
#pragma unroll
        for (int l = 0; l < NLBL; l++) {
            raw[l] = g_label_sums[b][l][t];
            m[l] = raw[l] * inv[l];
            sall += raw[l];
        }
        sall *= (1.f / (float)HW);
        float part[NPD];
        int k = 0;
#pragma unroll
        for (int l1 = 0; l1 < NLBL; l1++)
#pragma unroll
            for (int l2 = l1; l2 < NLBL; l2++) part[k++] = m[l1] * m[l2];
        part[28] = sall * sall;
#pragma unroll
        for (int i = 0; i < NPD; i++)
#pragma unroll
            for (int o = 16; o > 0; o >>= 1) part[i] += __shfl_xor_sync(0xffffffffu, part[i], o);
        __shared__ float acc[NPD];
        if (t < NPD) acc[t] = 0.f;
        __syncthreads();
        if (lane == 0) {
#pragma unroll
            for (int i = 0; i < NPD; i++) atomicAdd(&acc[i], part[i]);
        }
        __syncthreads();
        if (t < NPD) g_pd[b][t] = acc[t];
    }
}

// ---------------------------------------------------------------------------
// finalize: pure scalar math. rn2 == 1 => q_l = cnt_l, q_all = HW, so
// var_l = 1 - ||mean_l||^2 and var_all = 1 - ||mean_all||^2.
// ---------------------------------------------------------------------------
__global__ void finalize_kernel(const float* __restrict__ is_forged, float* __restrict__ out) {
    __shared__ float sc[BATCH], scv[BATCH], sp[BATCH], spv[BATCH], un[BATCH], unv[BATCH];
    int t = threadIdx.x;
    if (t < BATCH) {
        int b = t;
        float na = g_anchor_cnt[b];
        float supcon = g_supcon_sum[b] / fmaxf(na, 1.f);
        float supcon_valid = (na > 0.f) ? 1.f : 0.f;

        float pd[NPD];
#pragma unroll
        for (int i = 0; i < NPD; i++) pd[i] = g_pd[b][i];
        float cnt[NLBL], cn[NLBL];
#pragma unroll
        for (int l = 0; l < NLBL; l++) {
            cnt[l] = g_cnt[b][l];
            cn[l] = pd[PD(l, l)];
        }
        float terms = 0.f, npairs = 0.f;
        int npresent = 0;
#pragma unroll
        for (int l = 0; l < NLBL; l++) if (cnt[l] > 0.f) npresent++;
#pragma unroll
        for (int l1 = 0; l1 < NLBL; l1++)
#pragma unroll
            for (int l2 = l1 + 1; l2 < NLBL; l2++) {
                if (cnt[l1] > 0.f && cnt[l2] > 0.f) {
                    float sq = cn[l1] + cn[l2] - 2.f * pd[PD(l1, l2)];
                    float dd = sqrtf(fmaxf(sq, 0.f));
                    terms += fmaxf(SEPM - dd, 0.f);
                    npairs += 1.f;
                }
            }
        float sep = terms / fmaxf(npairs, 1.f);
        float sep_valid = (npresent >= 2) ? 1.f : 0.f;

        float uni, univ;
        if (is_forged[b] >= 0.5f) {
            float inst = 0.f, nl = 0.f;
#pragma unroll
            for (int l = 0; l < NLBL; l++) {
                float var = 1.0f - cn[l];      // q_l/cnt_l == 1 (unit-norm rows)
                if (cnt[l] >= 2.f && var > UNITH) { inst += var - UNITH; nl += 1.f; }
            }
            uni = inst / fmaxf(nl, 1.f);
            univ = (nl > 0.f) ? 1.f : 0.f;
        } else {
            float var_all = 1.0f - pd[28];     // q_all/HW == 1
            uni = (var_all > UNITH) ? (var_all - UNITH) : 0.f;
            univ = (var_all > UNITH) ? 1.f : 0.f;
        }

        sc[b] = supcon * supcon_valid; scv[b] = supcon_valid;
        sp[b] = sep * sep_valid;       spv[b] = sep_valid;
        un[b] = uni * univ;            unv[b] = univ;
    }
    __syncthreads();
    if (t == 0) {
        float a = 0.f, av = 0.f, s2 = 0.f, sv = 0.f, u = 0.f, uv = 0.f;
        for (int b = 0; b < BATCH; b++) {
            a += sc[b]; av += scv[b];
            s2 += sp[b]; sv += spv[b];
            u += un[b]; uv += unv[b];
        }
        float supcon = (av > 0.f) ? a / fmaxf(av, 1.f) : 0.f;
        float sep = (sv > 0.f) ? s2 / fmaxf(sv, 1.f) : 0.f;
        float uni = (uv > 0.f) ? u / fmaxf(uv, 1.f) : 0.f;
        out[0] = 1.0f * supcon + 0.5f * sep + 0.5f * uni;
    }
}

// ---------------------------------------------------------------------------
extern "C" void kernel_launch(void* const* d_in, const int* in_sizes, int n_in,
                              void* d_out, int out_size) {
    const float* emb   = (const float*)d_in[0];   // (16,33,33,512) f32
    const float* masks = (const float*)d_in[1];   // (16,6,33,33) f32
    const float* isf   = (const float*)d_in[2];   // (16,) f32
    float* out = (float*)d_out;

    cudaFuncSetAttribute(supcon_mma_kernel,
                         cudaFuncAttributeMaxDynamicSharedMemorySize, SM_TOTAL);

    prep_kernel<<<PBLK, 256>>>(masks);                                 // 0
    cvt_kernel<<<CVTBLK, 256>>>(emb);                                  // 1
    labels_kernel<<<(BATCH * HW + 255) / 256, 256>>>(masks);           // 2
    supcon_mma_kernel<<<dim3(NTILEPAIRS, BATCH), 512, SM_TOTAL>>>();   // 3 (ncu slot)
    centroid_kernel<<<dim3(CCHUNK, NLBL, BATCH), 512>>>();             // 4
    rowpd_kernel<<<2 * BATCH, 512>>>();                                // 5
    finalize_kernel<<<1, 32>>>(isf, out);                              // 6
}